// round 1
// baseline (speedup 1.0000x reference)
#include <cuda_runtime.h>
#include <cuda_bf16.h>

// Problem constants (from reference): N=50000, E=800000, IN=128, OUT=200
#define NN   50000
#define FD   128
#define OD   200
#define CAP  96          // max in-degree bucket capacity (Poisson(16); P(>=96) ~ 0)

// ---------------- device scratch (static allocation; no cudaMalloc) -------
__device__ float d_deg[NN];
__device__ int   d_cnt[NN];
__device__ int   d_bsrc[(size_t)NN * CAP];    // per-dst bucketed src ids
__device__ float d_bnorm[(size_t)NN * CAP];   // per-dst bucketed edge norms
__device__ float d_tx1[(size_t)NN * FD];
__device__ float d_tx2[(size_t)NN * FD];

// ---------------- zero deg/cnt -------------------------------------------
__global__ void zero_kernel(int n) {
    int i = blockIdx.x * blockDim.x + threadIdx.x;
    if (i < n) { d_deg[i] = 0.f; d_cnt[i] = 0; }
}

// ---------------- degree by src ------------------------------------------
__global__ void deg_kernel(const int* __restrict__ src, const float* __restrict__ w, int E) {
    int e = blockIdx.x * blockDim.x + threadIdx.x;
    if (e < E) atomicAdd(&d_deg[src[e]], w[e]);
}

// ---------------- norm + bucket fill (CSR-free, padded buckets) ----------
__global__ void fill_kernel(const int* __restrict__ src, const int* __restrict__ dst,
                            const float* __restrict__ w, int E) {
    int e = blockIdx.x * blockDim.x + threadIdx.x;
    if (e >= E) return;
    int s = src[e], d = dst[e];
    float ds = d_deg[s], dd = d_deg[d];
    float is = ds > 0.f ? rsqrtf(ds) : 0.f;
    float id = dd > 0.f ? rsqrtf(dd) : 0.f;
    float nrm = -is * w[e] * id;
    int slot = atomicAdd(&d_cnt[d], 1);
    if (slot < CAP) {
        d_bsrc[(size_t)d * CAP + slot]  = s;
        d_bnorm[(size_t)d * CAP + slot] = nrm;
    }
}

// ---------------- gather SpMM: out[dst] = sum norm * h[src] --------------
// MODE 0: d_tx1 = L^ @ x        (h = x)
// MODE 1: d_tx2 = 2*(L^ @ tx1) - x
template <int MODE>
__global__ void spmm_kernel(const float* __restrict__ x) {
    const float* h   = (MODE == 0) ? x : d_tx1;
    float*       out = (MODE == 0) ? d_tx1 : d_tx2;

    int node = blockIdx.x;
    int f    = threadIdx.x;           // 128 threads = one feature row
    __shared__ int   ssrc[CAP];
    __shared__ float snrm[CAP];

    int cnt = d_cnt[node];
    if (cnt > CAP) cnt = CAP;
    if (f < cnt) {
        ssrc[f] = d_bsrc[(size_t)node * CAP + f];
        snrm[f] = d_bnorm[(size_t)node * CAP + f];
    }
    __syncthreads();

    float acc = 0.f;
    int j = 0;
    for (; j + 4 <= cnt; j += 4) {
        float a0 = h[(size_t)ssrc[j+0] * FD + f];
        float a1 = h[(size_t)ssrc[j+1] * FD + f];
        float a2 = h[(size_t)ssrc[j+2] * FD + f];
        float a3 = h[(size_t)ssrc[j+3] * FD + f];
        acc += snrm[j+0] * a0;
        acc += snrm[j+1] * a1;
        acc += snrm[j+2] * a2;
        acc += snrm[j+3] * a3;
    }
    for (; j < cnt; j++)
        acc += snrm[j] * h[(size_t)ssrc[j] * FD + f];

    size_t o = (size_t)node * FD + f;
    if (MODE == 0) out[o] = acc;
    else           out[o] = 2.f * acc - x[o];
}

// ---------------- fp32 tiled GEMM: out = sum_kb A_kb @ W_kb + bias ------
// A_kb in {x, tx1, tx2} (each N x 128), W_kb is 128 x 200 row-major.
#define BM 128
#define BN 128
#define BK 16
#define TM 8
#define TN 8

__global__ __launch_bounds__(256) void gemm_kernel(
    const float* __restrict__ A0,
    const float* __restrict__ W0, const float* __restrict__ W1, const float* __restrict__ W2,
    const float* __restrict__ bias, float* __restrict__ out,
    int M, int Kblocks)
{
    __shared__ float As[BK][BM + 4];   // padded to soften store conflicts
    __shared__ float Bs[BK][BN];

    const float* Aptrs[3] = {A0, d_tx1, d_tx2};
    const float* Wptrs[3] = {W0, W1, W2};

    int bm = blockIdx.y * BM;
    int bn = blockIdx.x * BN;
    int tid = threadIdx.x;
    int tr = (tid >> 4) * TM;   // 16 row groups
    int tc = (tid & 15) * TN;   // 16 col groups

    float acc[TM][TN];
#pragma unroll
    for (int m = 0; m < TM; m++)
#pragma unroll
        for (int n = 0; n < TN; n++) acc[m][n] = 0.f;

    for (int kb = 0; kb < Kblocks; kb++) {
        const float* A = Aptrs[kb];
        const float* W = Wptrs[kb];
        for (int kt = 0; kt < FD; kt += BK) {
            // A tile: 128 rows x 16 k, vectorized float4 loads, stored transposed
#pragma unroll
            for (int i = 0; i < 2; i++) {
                int lin = tid + i * 256;       // 0..511 float4 slots
                int row = lin >> 2;            // 0..127
                int k4  = (lin & 3) << 2;      // 0,4,8,12
                float4 v = make_float4(0.f, 0.f, 0.f, 0.f);
                int gr = bm + row;
                if (gr < M) v = *(const float4*)(A + (size_t)gr * FD + kt + k4);
                As[k4 + 0][row] = v.x;
                As[k4 + 1][row] = v.y;
                As[k4 + 2][row] = v.z;
                As[k4 + 3][row] = v.w;
            }
            // B tile: 16 k-rows x 128 cols (guard OD=200)
#pragma unroll
            for (int i = 0; i < 8; i++) {
                int lin = tid + i * 256;       // 0..2047
                int kr = lin >> 7;             // 0..15
                int cc = lin & 127;
                int gc = bn + cc;
                Bs[kr][cc] = (gc < OD) ? W[(size_t)(kt + kr) * OD + gc] : 0.f;
            }
            __syncthreads();
#pragma unroll
            for (int k = 0; k < BK; k++) {
                float ar[TM], br[TN];
#pragma unroll
                for (int m = 0; m < TM; m++) ar[m] = As[k][tr + m];
#pragma unroll
                for (int n = 0; n < TN; n++) br[n] = Bs[k][tc + n];
#pragma unroll
                for (int m = 0; m < TM; m++)
#pragma unroll
                    for (int n = 0; n < TN; n++)
                        acc[m][n] += ar[m] * br[n];
            }
            __syncthreads();
        }
    }

#pragma unroll
    for (int m = 0; m < TM; m++) {
        int r = bm + tr + m;
        if (r >= M) continue;
#pragma unroll
        for (int n = 0; n < TN; n++) {
            int c = bn + tc + n;
            if (c < OD) out[(size_t)r * OD + c] = acc[m][n] + bias[c];
        }
    }
}

static inline int cdiv(int a, int b) { return (a + b - 1) / b; }

extern "C" void kernel_launch(void* const* d_in, const int* in_sizes, int n_in,
                              void* d_out, int out_size) {
    const float* x    = (const float*)d_in[0];
    const int*   ei   = (const int*)  d_in[1];   // [2, E]: src then dst
    const float* ew   = (const float*)d_in[2];
    const float* w1_0 = (const float*)d_in[3];
    const float* b1   = (const float*)d_in[4];
    const float* w2_0 = (const float*)d_in[5];
    const float* w2_1 = (const float*)d_in[6];
    const float* b2   = (const float*)d_in[7];
    const float* w3_0 = (const float*)d_in[8];
    const float* w3_1 = (const float*)d_in[9];
    const float* w3_2 = (const float*)d_in[10];
    const float* b3   = (const float*)d_in[11];
    float* out = (float*)d_out;

    int E = in_sizes[2];
    int N = in_sizes[0] / FD;
    const int* src = ei;
    const int* dst = ei + E;

    zero_kernel<<<cdiv(N, 256), 256>>>(N);
    deg_kernel<<<cdiv(E, 256), 256>>>(src, ew, E);
    fill_kernel<<<cdiv(E, 256), 256>>>(src, dst, ew, E);
    spmm_kernel<0><<<N, FD>>>(x);
    spmm_kernel<1><<<N, FD>>>(x);

    dim3 g(cdiv(OD, BN), cdiv(N, BM));
    size_t NM = (size_t)N * OD;
    gemm_kernel<<<g, 256>>>(x, w1_0, nullptr, nullptr, b1, out,          N, 1);
    gemm_kernel<<<g, 256>>>(x, w2_0, w2_1,   nullptr, b2, out + NM,     N, 2);
    gemm_kernel<<<g, 256>>>(x, w3_0, w3_1,   w3_2,    b3, out + 2 * NM, N, 3);
}

// round 3
// speedup vs baseline: 2.9526x; 2.9526x over previous
#include <cuda_runtime.h>
#include <cuda_bf16.h>
#include <cstdint>

// Problem constants: N=50000, E=800000, IN=128, OUT=200
#define NN   50000
#define FD   128
#define OD   200
#define ODP  208          // padded N
#define CAP  96
#define MT   128

// ================= device scratch (no cudaMalloc allowed) ================
__device__ float d_deg[NN];
__device__ int   d_cnt[NN];
__device__ int   d_bsrc[(size_t)NN * CAP];
__device__ float d_bnorm[(size_t)NN * CAP];
__device__ float d_tx1[(size_t)NN * FD];
// bf16 hi/lo operand forms of tx0(x), tx1, tx2
__device__ __nv_bfloat16 d_ah[3][(size_t)NN * FD];
__device__ __nv_bfloat16 d_al[3][(size_t)NN * FD];
// weights as [FD=128 rows (k)][ODP=208 cols (n)] bf16 hi/lo, zero-padded cols
// order: w1_0, w2_0, w2_1, w3_0, w3_1, w3_2
__device__ __nv_bfloat16 d_wh[6][(size_t)FD * ODP];
__device__ __nv_bfloat16 d_wl[6][(size_t)FD * ODP];

// ================= helpers ==============================================
__device__ __forceinline__ uint32_t smem_u32(const void* p) {
    uint32_t a;
    asm("{ .reg .u64 t; cvta.to.shared.u64 t, %1; cvt.u32.u64 %0, t; }" : "=r"(a) : "l"(p));
    return a;
}
__device__ __forceinline__ void cp_async16(uint32_t saddr, const void* gaddr, int srcBytes) {
    asm volatile("cp.async.cg.shared.global [%0], [%1], 16, %2;"
                 :: "r"(saddr), "l"(gaddr), "r"(srcBytes) : "memory");
}
#define CP_COMMIT() asm volatile("cp.async.commit_group;" ::: "memory")

__device__ __forceinline__ void ldsm4(uint32_t* r, uint32_t addr) {
    asm volatile("ldmatrix.sync.aligned.m8n8.x4.shared.b16 {%0,%1,%2,%3}, [%4];"
                 : "=r"(r[0]), "=r"(r[1]), "=r"(r[2]), "=r"(r[3]) : "r"(addr));
}
__device__ __forceinline__ void ldsm4t(uint32_t* r, uint32_t addr) {
    asm volatile("ldmatrix.sync.aligned.m8n8.x4.trans.shared.b16 {%0,%1,%2,%3}, [%4];"
                 : "=r"(r[0]), "=r"(r[1]), "=r"(r[2]), "=r"(r[3]) : "r"(addr));
}
__device__ __forceinline__ void mma16816(float* c, const uint32_t* a, const uint32_t* b) {
    asm volatile("mma.sync.aligned.m16n8k16.row.col.f32.bf16.bf16.f32 "
                 "{%0,%1,%2,%3}, {%4,%5,%6,%7}, {%8,%9}, {%0,%1,%2,%3};"
                 : "+f"(c[0]), "+f"(c[1]), "+f"(c[2]), "+f"(c[3])
                 : "r"(a[0]), "r"(a[1]), "r"(a[2]), "r"(a[3]), "r"(b[0]), "r"(b[1]));
}

// ================= graph preprocessing ==================================
__global__ void zero_kernel(int n) {
    int i = blockIdx.x * blockDim.x + threadIdx.x;
    if (i < n) { d_deg[i] = 0.f; d_cnt[i] = 0; }
}
__global__ void deg_kernel(const int* __restrict__ src, const float* __restrict__ w, int E) {
    int e = blockIdx.x * blockDim.x + threadIdx.x;
    if (e < E) atomicAdd(&d_deg[src[e]], w[e]);
}
__global__ void fill_kernel(const int* __restrict__ src, const int* __restrict__ dst,
                            const float* __restrict__ w, int E) {
    int e = blockIdx.x * blockDim.x + threadIdx.x;
    if (e >= E) return;
    int s = src[e], d = dst[e];
    float ds = d_deg[s], dd = d_deg[d];
    float is = ds > 0.f ? rsqrtf(ds) : 0.f;
    float id = dd > 0.f ? rsqrtf(dd) : 0.f;
    float nrm = -is * w[e] * id;
    int slot = atomicAdd(&d_cnt[d], 1);
    if (slot < CAP) {
        d_bsrc[(size_t)d * CAP + slot]  = s;
        d_bnorm[(size_t)d * CAP + slot] = nrm;
    }
}

__device__ __forceinline__ void split_store(__nv_bfloat16* ph, __nv_bfloat16* pl,
                                            size_t i, float v) {
    __nv_bfloat16 h = __float2bfloat16_rn(v);
    ph[i] = h;
    pl[i] = __float2bfloat16_rn(v - __bfloat162float(h));
}

__global__ void convert_x_kernel(const float* __restrict__ x, int total) {
    int i = blockIdx.x * blockDim.x + threadIdx.x;
    if (i < total) split_store(d_ah[0], d_al[0], i, x[i]);
}

// weights fp32 [k=128][n=200] -> bf16 hi/lo [k=128][n=208] zero padded
__global__ void wprep_kernel(const float* w0, const float* w1, const float* w2,
                             const float* w3, const float* w4, const float* w5) {
    const float* ws[6] = {w0, w1, w2, w3, w4, w5};
    int i = blockIdx.x * blockDim.x + threadIdx.x;
    if (i >= 6 * FD * ODP) return;
    int m = i / (FD * ODP);
    int r = i % (FD * ODP);
    int k = r / ODP, n = r % ODP;
    float v = (n < OD) ? ws[m][(size_t)k * OD + n] : 0.f;
    split_store(d_wh[m], d_wl[m], r, v);
}

// gather SpMM. MODE 0: tx1 = L^x (fp32 + hi/lo).  MODE 1: tx2 = 2 L^ tx1 - x (hi/lo)
template <int MODE>
__global__ void spmm_kernel(const float* __restrict__ x) {
    const float* h = (MODE == 0) ? x : d_tx1;
    int node = blockIdx.x;
    int f    = threadIdx.x;
    __shared__ int   ssrc[CAP];
    __shared__ float snrm[CAP];
    int cnt = d_cnt[node];
    if (cnt > CAP) cnt = CAP;
    if (f < cnt) {
        ssrc[f] = d_bsrc[(size_t)node * CAP + f];
        snrm[f] = d_bnorm[(size_t)node * CAP + f];
    }
    __syncthreads();
    float acc = 0.f;
    int j = 0;
    for (; j + 4 <= cnt; j += 4) {
        acc += snrm[j+0] * h[(size_t)ssrc[j+0] * FD + f];
        acc += snrm[j+1] * h[(size_t)ssrc[j+1] * FD + f];
        acc += snrm[j+2] * h[(size_t)ssrc[j+2] * FD + f];
        acc += snrm[j+3] * h[(size_t)ssrc[j+3] * FD + f];
    }
    for (; j < cnt; j++) acc += snrm[j] * h[(size_t)ssrc[j] * FD + f];
    size_t o = (size_t)node * FD + f;
    if (MODE == 0) {
        d_tx1[o] = acc;
        split_store(d_ah[1], d_al[1], o, acc);
    } else {
        float v = 2.f * acc - x[o];
        split_store(d_ah[2], d_al[2], o, v);
    }
}

// ================= mma.sync GEMM ========================================
// smem: A rows 272B (256B data + 16 pad), B rows 432B (208 data cols + 8 pad)
#define AROW 272
#define BROW 432
#define SA_HI 0
#define SA_LO (128 * AROW)                 // 34816
#define SB_HI (2 * 128 * AROW)             // 69632
#define SB_LO (SB_HI + 128 * BROW)         // 124928
#define S_BIAS (SB_LO + 128 * BROW)        // 180224
#define S_TOTAL (S_BIAS + 1024)            // 181248

struct GemmSmemPtrs {
    uint32_t sb;
    const __nv_bfloat16 *gah, *gal, *gbh, *gbl;
    int bm, nnodes;
};

// issue chunk ks (k rows 16ks..16ks+15) loads via cp.async, one group
__device__ __forceinline__ void issue_chunk(const GemmSmemPtrs& P, int ks, int tid) {
    // A hi / A lo: 256 uint4 each (128 rows x 32B)
    {
        int row = tid >> 1, c = tid & 1;
        int gm = P.bm + row;
        int sz = (gm < P.nnodes) ? 16 : 0;
        const __nv_bfloat16* ga = P.gah + (size_t)min(gm, P.nnodes - 1) * FD + ks * 16 + c * 8;
        const __nv_bfloat16* gl = P.gal + (size_t)min(gm, P.nnodes - 1) * FD + ks * 16 + c * 8;
        uint32_t so = row * AROW + ks * 32 + c * 16;
        cp_async16(P.sb + SA_HI + so, ga, sz);
        cp_async16(P.sb + SA_LO + so, gl, sz);
    }
    // B hi / B lo: 416 uint4 each (16 rows x 26)
    for (int u = tid; u < 416; u += 256) {
        int r16 = u / 26, c = u - r16 * 26;
        int grow = ks * 16 + r16;
        uint32_t so = grow * BROW + c * 16;
        cp_async16(P.sb + SB_HI + so, P.gbh + (size_t)grow * ODP + c * 8, 16);
        cp_async16(P.sb + SB_LO + so, P.gbl + (size_t)grow * ODP + c * 8, 16);
    }
    CP_COMMIT();
}

__device__ __forceinline__ void consume_chunk(uint32_t sb, int ks, int l,
                                              int mbase, int nbase,
                                              float acc[2][13][4]) {
    uint32_t ah[2][4], al[2][4], bb[14][2];
    // A frags (hi and lo)
#pragma unroll
    for (int i = 0; i < 2; i++) {
        uint32_t ra = sb + SA_HI + (mbase + i * 16 + (l & 15)) * AROW + ks * 32 + (l >> 4) * 16;
        ldsm4(ah[i], ra);
        ldsm4(al[i], ra + (SA_LO - SA_HI));
    }
    int krow = ks * 16 + (l & 15);
    uint32_t rbbase = sb + krow * BROW + (((l >> 4) & 1) * 16);
    // B hi frags
#pragma unroll
    for (int j2 = 0; j2 < 7; j2++)
        ldsm4t(&bb[j2 * 2][0], rbbase + SB_HI + (nbase + j2 * 16) * 2);
    // hi*hi and lo*hi
#pragma unroll
    for (int i = 0; i < 2; i++)
#pragma unroll
        for (int j = 0; j < 13; j++) mma16816(acc[i][j], ah[i], bb[j]);
#pragma unroll
    for (int i = 0; i < 2; i++)
#pragma unroll
        for (int j = 0; j < 13; j++) mma16816(acc[i][j], al[i], bb[j]);
    // B lo frags (reuse regs), hi*lo
#pragma unroll
    for (int j2 = 0; j2 < 7; j2++)
        ldsm4t(&bb[j2 * 2][0], rbbase + SB_LO + (nbase + j2 * 16) * 2);
#pragma unroll
    for (int i = 0; i < 2; i++)
#pragma unroll
        for (int j = 0; j < 13; j++) mma16816(acc[i][j], ah[i], bb[j]);
}

__global__ __launch_bounds__(256, 1) void gemm_kernel(
    const float* __restrict__ b1, const float* __restrict__ b2, const float* __restrict__ b3,
    float* __restrict__ out, int nnodes)
{
    extern __shared__ char smem[];
    const uint32_t sb = smem_u32(smem);
    const int tid = threadIdx.x;
    const int l = tid & 31;
    const int wid = tid >> 5;
    const int s = blockIdx.y;
    const int bm = blockIdx.x * MT;
    const int Kb = s + 1;
    const int wbase = s * (s + 1) / 2;
    float* sbias = (float*)(smem + S_BIAS);

    const float* bp = (s == 0) ? b1 : (s == 1) ? b2 : b3;
    if (tid < OD) sbias[tid] = bp[tid];
    // zero B pad cols 208-215 (bytes 416..431), hi & lo, once
    if (tid < 128)      *(uint4*)(smem + SB_HI + tid * BROW + 416) = make_uint4(0, 0, 0, 0);
    else                *(uint4*)(smem + SB_LO + (tid - 128) * BROW + 416) = make_uint4(0, 0, 0, 0);

    const int wm = wid >> 1, wn = wid & 1;
    const int mbase = wm * 32, nbase = wn * 104;

    float acc[2][13][4];
#pragma unroll
    for (int i = 0; i < 2; i++)
#pragma unroll
        for (int j = 0; j < 13; j++)
#pragma unroll
            for (int r = 0; r < 4; r++) acc[i][j][r] = 0.f;

    for (int kb = 0; kb < Kb; kb++) {
        GemmSmemPtrs P;
        P.sb = sb; P.bm = bm; P.nnodes = nnodes;
        P.gah = d_ah[kb]; P.gal = d_al[kb];
        P.gbh = d_wh[wbase + kb]; P.gbl = d_wl[wbase + kb];
        __syncthreads();                 // previous kb's mma reads done
        for (int ks = 0; ks < 8; ks++) issue_chunk(P, ks, tid);

#define STEP(KS, WG) \
        asm volatile("cp.async.wait_group " #WG ";" ::: "memory"); \
        __syncthreads(); \
        consume_chunk(sb, KS, l, mbase, nbase, acc);
        STEP(0, 7) STEP(1, 6) STEP(2, 5) STEP(3, 4)
        STEP(4, 3) STEP(5, 2) STEP(6, 1) STEP(7, 0)
#undef STEP
    }

    // epilogue
#pragma unroll
    for (int i = 0; i < 2; i++) {
        int row0 = bm + mbase + i * 16 + (l >> 2);
#pragma unroll
        for (int j = 0; j < 13; j++) {
            int col = nbase + j * 8 + (l & 3) * 2;
            if (col >= OD) continue;
            float bc0 = sbias[col], bc1 = sbias[col + 1];
            if (row0 < nnodes) {
                float2 v = make_float2(acc[i][j][0] + bc0, acc[i][j][1] + bc1);
                *(float2*)(out + ((size_t)s * nnodes + row0) * OD + col) = v;
            }
            int row1 = row0 + 8;
            if (row1 < nnodes) {
                float2 v = make_float2(acc[i][j][2] + bc0, acc[i][j][3] + bc1);
                *(float2*)(out + ((size_t)s * nnodes + row1) * OD + col) = v;
            }
        }
    }
}

static inline int cdiv(int a, int b) { return (a + b - 1) / b; }

extern "C" void kernel_launch(void* const* d_in, const int* in_sizes, int n_in,
                              void* d_out, int out_size) {
    const float* x    = (const float*)d_in[0];
    const int*   ei   = (const int*)  d_in[1];
    const float* ew   = (const float*)d_in[2];
    const float* w1_0 = (const float*)d_in[3];
    const float* b1   = (const float*)d_in[4];
    const float* w2_0 = (const float*)d_in[5];
    const float* w2_1 = (const float*)d_in[6];
    const float* b2   = (const float*)d_in[7];
    const float* w3_0 = (const float*)d_in[8];
    const float* w3_1 = (const float*)d_in[9];
    const float* w3_2 = (const float*)d_in[10];
    const float* b3   = (const float*)d_in[11];
    float* out = (float*)d_out;

    int E = in_sizes[2];
    int N = in_sizes[0] / FD;
    if (N > NN) N = NN;
    const int* src = ei;
    const int* dst = ei + E;

    static int smem_set = 0;
    if (!smem_set) {
        cudaFuncSetAttribute(gemm_kernel, cudaFuncAttributeMaxDynamicSharedMemorySize, S_TOTAL);
        smem_set = 1;
    }

    zero_kernel<<<cdiv(N, 256), 256>>>(N);
    deg_kernel<<<cdiv(E, 256), 256>>>(src, ew, E);
    fill_kernel<<<cdiv(E, 256), 256>>>(src, dst, ew, E);
    convert_x_kernel<<<cdiv(N * FD, 256), 256>>>(x, N * FD);
    wprep_kernel<<<cdiv(6 * FD * ODP, 256), 256>>>(w1_0, w2_0, w2_1, w3_0, w3_1, w3_2);
    spmm_kernel<0><<<N, FD>>>(x);
    spmm_kernel<1><<<N, FD>>>(x);

    dim3 grid(cdiv(N, MT), 3);
    gemm_kernel<<<grid, 256, S_TOTAL>>>(b1, b2, b3, out, N);
}

// round 4
// speedup vs baseline: 3.5902x; 1.2160x over previous
#include <cuda_runtime.h>
#include <cuda_bf16.h>
#include <cstdint>

// Problem constants: N=50000, E=800000, IN=128, OUT=200
#define NN   50000
#define FD   128
#define OD   200
#define CAP  96
#define MT   128
#define NT   391                   // M tiles
#define NP   (NT * 128)            // padded nodes = 50048

// A operand image: [tile][chunk ks 0..7][row 0..127][48B], 32B data + 16B pad
#define AROW   48
#define ACH    (128 * AROW)        // 6144 B per chunk
#define ATILE  (8 * ACH)           // 49152 B per tile
#define AELEMS ((size_t)NT * ATILE / 2)
// B (weight) image: [k 0..127][216 cols bf16] = row 432B; chunk = 16 rows = 6912B
#define BCOLS  216
#define BROW   (BCOLS * 2)         // 432
#define BCH    (16 * BROW)         // 6912
#define BELEMS ((size_t)FD * BCOLS)

// ================= device scratch (no cudaMalloc allowed) ================
__device__ float d_deg[NN];
__device__ int   d_cnt[NN];
__device__ int   d_bsrc[(size_t)NN * CAP];
__device__ float d_bnorm[(size_t)NN * CAP];
__device__ __align__(16)   float d_tx1[(size_t)NN * FD];
// chunk-major bf16 hi/lo operand images of tx0(x), tx1, tx2 (zero-init covers pad rows)
__device__ __align__(1024) __nv_bfloat16 d_ah[3][AELEMS];
__device__ __align__(1024) __nv_bfloat16 d_al[3][AELEMS];
// weights hi/lo, order: w1_0, w2_0, w2_1, w3_0, w3_1, w3_2
__device__ __align__(1024) __nv_bfloat16 d_wh[6][BELEMS];
__device__ __align__(1024) __nv_bfloat16 d_wl[6][BELEMS];

// ================= helpers ==============================================
__device__ __forceinline__ uint32_t smem_u32(const void* p) {
    uint32_t a;
    asm("{ .reg .u64 t; cvta.to.shared.u64 t, %1; cvt.u32.u64 %0, t; }" : "=r"(a) : "l"(p));
    return a;
}
#define MBARRIER_INIT(mb, c) \
    asm volatile("mbarrier.init.shared.b64 [%0], %1;" :: "r"((uint32_t)(mb)), "r"((uint32_t)(c)) : "memory")
#define MBARRIER_EXPECT_TX(mb, tx) \
    asm volatile("mbarrier.arrive.expect_tx.shared.b64 _, [%0], %1;" :: "r"((uint32_t)(mb)), "r"((uint32_t)(tx)) : "memory")
#define BULK_G2S(dst, src, bytes, mb) \
    asm volatile("cp.async.bulk.shared::cta.global.mbarrier::complete_tx::bytes [%0], [%1], %2, [%3];" \
        :: "r"((uint32_t)(dst)), "l"(src), "r"((uint32_t)(bytes)), "r"((uint32_t)(mb)) : "memory")
#define MBARRIER_WAIT_PARITY(mb, ph) do {                                        \
    uint32_t _mb = (uint32_t)(mb), _ph = (uint32_t)(ph), _done;                  \
    asm volatile("{\n\t.reg .pred p;\n\t"                                        \
        "mbarrier.try_wait.parity.acquire.cta.shared::cta.b64 p, [%1], %2;\n\t"  \
        "selp.b32 %0, 1, 0, p;\n\t}" : "=r"(_done) : "r"(_mb), "r"(_ph) : "memory"); \
    if (!_done) {                                                                \
        asm volatile("{\n\t.reg .pred P1;\n\t"                                   \
            "W%=:\n\t"                                                           \
            "mbarrier.try_wait.parity.acquire.cta.shared::cta.b64 P1, [%0], %1, 0x989680;\n\t" \
            "@P1 bra.uni D%=;\n\t"                                               \
            "bra.uni W%=;\n\t"                                                   \
            "D%=:\n\t}" :: "r"(_mb), "r"(_ph) : "memory");                       \
    }                                                                            \
} while (0)

__device__ __forceinline__ void ldsm4(uint32_t* r, uint32_t addr) {
    asm volatile("ldmatrix.sync.aligned.m8n8.x4.shared.b16 {%0,%1,%2,%3}, [%4];"
                 : "=r"(r[0]), "=r"(r[1]), "=r"(r[2]), "=r"(r[3]) : "r"(addr));
}
__device__ __forceinline__ void ldsm4t(uint32_t* r, uint32_t addr) {
    asm volatile("ldmatrix.sync.aligned.m8n8.x4.trans.shared.b16 {%0,%1,%2,%3}, [%4];"
                 : "=r"(r[0]), "=r"(r[1]), "=r"(r[2]), "=r"(r[3]) : "r"(addr));
}
__device__ __forceinline__ void mma16816(float* c, const uint32_t* a, const uint32_t* b) {
    asm volatile("mma.sync.aligned.m16n8k16.row.col.f32.bf16.bf16.f32 "
                 "{%0,%1,%2,%3}, {%4,%5,%6,%7}, {%8,%9}, {%0,%1,%2,%3};"
                 : "+f"(c[0]), "+f"(c[1]), "+f"(c[2]), "+f"(c[3])
                 : "r"(a[0]), "r"(a[1]), "r"(a[2]), "r"(a[3]), "r"(b[0]), "r"(b[1]));
}

// ================= graph preprocessing ==================================
__global__ void zero_kernel(int n) {
    int i = blockIdx.x * blockDim.x + threadIdx.x;
    if (i < n) { d_deg[i] = 0.f; d_cnt[i] = 0; }
}
__global__ void deg_kernel(const int* __restrict__ src, const float* __restrict__ w, int E) {
    int e = blockIdx.x * blockDim.x + threadIdx.x;
    if (e < E) atomicAdd(&d_deg[src[e]], w[e]);
}
__global__ void fill_kernel(const int* __restrict__ src, const int* __restrict__ dst,
                            const float* __restrict__ w, int E) {
    int e = blockIdx.x * blockDim.x + threadIdx.x;
    if (e >= E) return;
    int s = src[e], d = dst[e];
    float ds = d_deg[s], dd = d_deg[d];
    float is = ds > 0.f ? rsqrtf(ds) : 0.f;
    float id = dd > 0.f ? rsqrtf(dd) : 0.f;
    float nrm = -is * w[e] * id;
    int slot = atomicAdd(&d_cnt[d], 1);
    if (slot < CAP) {
        d_bsrc[(size_t)d * CAP + slot]  = s;
        d_bnorm[(size_t)d * CAP + slot] = nrm;
    }
}

// split-store a float4 (features l*4 .. l*4+3 of one node row) into op's hi/lo images
__device__ __forceinline__ void store_split4(int op, int node, int l, float4 v) {
    int tile = node >> 7, r = node & 127, ks = l >> 2;
    size_t e = ((size_t)(tile * 8 + ks) * 128 + r) * 24 + (l & 3) * 4;
    __nv_bfloat16 h0 = __float2bfloat16_rn(v.x);
    __nv_bfloat16 h1 = __float2bfloat16_rn(v.y);
    __nv_bfloat16 h2 = __float2bfloat16_rn(v.z);
    __nv_bfloat16 h3 = __float2bfloat16_rn(v.w);
    __nv_bfloat16 l0 = __float2bfloat16_rn(v.x - __bfloat162float(h0));
    __nv_bfloat16 l1 = __float2bfloat16_rn(v.y - __bfloat162float(h1));
    __nv_bfloat16 l2 = __float2bfloat16_rn(v.z - __bfloat162float(h2));
    __nv_bfloat16 l3 = __float2bfloat16_rn(v.w - __bfloat162float(h3));
    __nv_bfloat162 hp0(h0, h1), hp1(h2, h3), lp0(l0, l1), lp1(l2, l3);
    uint2 H = make_uint2(*(uint32_t*)&hp0, *(uint32_t*)&hp1);
    uint2 L = make_uint2(*(uint32_t*)&lp0, *(uint32_t*)&lp1);
    *(uint2*)&d_ah[op][e] = H;
    *(uint2*)&d_al[op][e] = L;
}

__global__ void convert_x_kernel(const float4* __restrict__ x4, int nwords) {
    int i = blockIdx.x * blockDim.x + threadIdx.x;
    if (i >= nwords) return;
    store_split4(0, i >> 5, i & 31, x4[i]);
}

// weights fp32 [k=128][n=200] -> bf16 hi/lo [k=128][n=216] zero padded
__global__ void wprep_kernel(const float* w0, const float* w1, const float* w2,
                             const float* w3, const float* w4, const float* w5) {
    const float* ws[6] = {w0, w1, w2, w3, w4, w5};
    int i = blockIdx.x * blockDim.x + threadIdx.x;
    if (i >= 6 * FD * BCOLS) return;
    int m = i / (FD * BCOLS);
    int r = i % (FD * BCOLS);
    int k = r / BCOLS, n = r % BCOLS;
    float v = (n < OD) ? ws[m][(size_t)k * OD + n] : 0.f;
    __nv_bfloat16 h = __float2bfloat16_rn(v);
    d_wh[m][r] = h;
    d_wl[m][r] = __float2bfloat16_rn(v - __bfloat162float(h));
}

// gather SpMM, warp-per-node, float4 lanes.
// MODE 0: tx1 = L^x (fp32 row-major + hi/lo image).  MODE 1: tx2 = 2 L^ tx1 - x (image only)
template <int MODE>
__global__ __launch_bounds__(256) void spmm_kernel(const float* __restrict__ x, int nnodes) {
    __shared__ int   ssrc[8][CAP];
    __shared__ float snrm[8][CAP];
    int w = threadIdx.x >> 5, l = threadIdx.x & 31;
    int node = blockIdx.x * 8 + w;
    if (node >= nnodes) return;

    int cnt = d_cnt[node];
    if (cnt > CAP) cnt = CAP;
    for (int j = l; j < cnt; j += 32) {
        ssrc[w][j] = d_bsrc[(size_t)node * CAP + j];
        snrm[w][j] = d_bnorm[(size_t)node * CAP + j];
    }
    __syncwarp();

    const float4* h4 = (MODE == 0) ? (const float4*)x : (const float4*)d_tx1;
    float4 acc = make_float4(0.f, 0.f, 0.f, 0.f);
    int j = 0;
    for (; j + 4 <= cnt; j += 4) {
        float4 v0 = h4[(size_t)ssrc[w][j+0] * 32 + l];
        float4 v1 = h4[(size_t)ssrc[w][j+1] * 32 + l];
        float4 v2 = h4[(size_t)ssrc[w][j+2] * 32 + l];
        float4 v3 = h4[(size_t)ssrc[w][j+3] * 32 + l];
        float n0 = snrm[w][j+0], n1 = snrm[w][j+1], n2 = snrm[w][j+2], n3 = snrm[w][j+3];
        acc.x += n0*v0.x + n1*v1.x + n2*v2.x + n3*v3.x;
        acc.y += n0*v0.y + n1*v1.y + n2*v2.y + n3*v3.y;
        acc.z += n0*v0.z + n1*v1.z + n2*v2.z + n3*v3.z;
        acc.w += n0*v0.w + n1*v1.w + n2*v2.w + n3*v3.w;
    }
    for (; j < cnt; j++) {
        float4 v = h4[(size_t)ssrc[w][j] * 32 + l];
        float n0 = snrm[w][j];
        acc.x += n0*v.x; acc.y += n0*v.y; acc.z += n0*v.z; acc.w += n0*v.w;
    }

    if (MODE == 0) {
        ((float4*)d_tx1)[(size_t)node * 32 + l] = acc;
        store_split4(1, node, l, acc);
    } else {
        float4 xv = ((const float4*)x)[(size_t)node * 32 + l];
        float4 t = make_float4(2.f*acc.x - xv.x, 2.f*acc.y - xv.y,
                               2.f*acc.z - xv.z, 2.f*acc.w - xv.w);
        store_split4(2, node, l, t);
    }
}

// ================= bulk-copy mma.sync GEMM ==============================
#define SA_HI 0
#define SA_LO (8 * ACH)                    // 49152
#define SB_HI (2 * 8 * ACH)                // 98304
#define SB_LO (SB_HI + 8 * BCH)            // 153600
#define S_BIAS (SB_LO + 8 * BCH)           // 208896
#define S_MBAR (S_BIAS + 896)              // 209792
#define S_TOTAL (S_MBAR + 64)              // 209856

__device__ __forceinline__ void consume_chunk(uint32_t sb, int c, int l,
                                              int mbase, int nbase,
                                              float acc[2][13][4]) {
    uint32_t ah[2][4], al[2][4], bb[14][2];
    uint32_t aBase = sb + SA_HI + c * ACH;
#pragma unroll
    for (int i = 0; i < 2; i++) {
        uint32_t ra = aBase + (mbase + i * 16 + (l & 15)) * AROW + (l >> 4) * 16;
        ldsm4(ah[i], ra);
        ldsm4(al[i], ra + (SA_LO - SA_HI));
    }
    uint32_t bBase = sb + SB_HI + c * BCH + (l & 15) * BROW + (l >> 4) * 16;
#pragma unroll
    for (int j2 = 0; j2 < 7; j2++)
        ldsm4t(&bb[j2 * 2][0], bBase + (nbase + j2 * 16) * 2);
#pragma unroll
    for (int i = 0; i < 2; i++)
#pragma unroll
        for (int j = 0; j < 13; j++) mma16816(acc[i][j], ah[i], bb[j]);
#pragma unroll
    for (int i = 0; i < 2; i++)
#pragma unroll
        for (int j = 0; j < 13; j++) mma16816(acc[i][j], al[i], bb[j]);
#pragma unroll
    for (int j2 = 0; j2 < 7; j2++)
        ldsm4t(&bb[j2 * 2][0], bBase + (SB_LO - SB_HI) + (nbase + j2 * 16) * 2);
#pragma unroll
    for (int i = 0; i < 2; i++)
#pragma unroll
        for (int j = 0; j < 13; j++) mma16816(acc[i][j], ah[i], bb[j]);
}

__global__ __launch_bounds__(256, 1) void gemm_kernel(
    const float* __restrict__ b1, const float* __restrict__ b2, const float* __restrict__ b3,
    float* __restrict__ out, int nnodes)
{
    extern __shared__ char smem[];
    const uint32_t sb = smem_u32(smem);
    const int tid = threadIdx.x;
    const int l = tid & 31;
    const int wid = tid >> 5;
    const int s = blockIdx.y;
    const int tile = blockIdx.x;
    const int bm = tile * MT;
    const int Kb = s + 1;
    const int wbase = s * (s + 1) / 2;
    float* sbias = (float*)(smem + S_BIAS);

    const float* bp = (s == 0) ? b1 : (s == 1) ? b2 : b3;
    if (tid < OD) sbias[tid] = bp[tid];
    if (tid == 0) {
#pragma unroll
        for (int c = 0; c < 8; c++) MBARRIER_INIT(sb + S_MBAR + c * 8, 1);
    }
    __syncthreads();

    const int wm = wid >> 1, wn = wid & 1;
    const int mbase = wm * 32, nbase = wn * 104;

    float acc[2][13][4];
#pragma unroll
    for (int i = 0; i < 2; i++)
#pragma unroll
        for (int j = 0; j < 13; j++)
#pragma unroll
            for (int r = 0; r < 4; r++) acc[i][j][r] = 0.f;

    for (int kb = 0; kb < Kb; kb++) {
        if (kb) __syncthreads();           // prior chunk buffers fully consumed
        if (tid == 0) {
            const char* gah = (const char*)d_ah[kb] + (size_t)tile * ATILE;
            const char* gal = (const char*)d_al[kb] + (size_t)tile * ATILE;
            const char* gbh = (const char*)d_wh[wbase + kb];
            const char* gbl = (const char*)d_wl[wbase + kb];
#pragma unroll
            for (int c = 0; c < 8; c++) {
                uint32_t mb = sb + S_MBAR + c * 8;
                MBARRIER_EXPECT_TX(mb, 2 * ACH + 2 * BCH);
                BULK_G2S(sb + SA_HI + c * ACH, gah + c * ACH, ACH, mb);
                BULK_G2S(sb + SA_LO + c * ACH, gal + c * ACH, ACH, mb);
                BULK_G2S(sb + SB_HI + c * BCH, gbh + c * BCH, BCH, mb);
                BULK_G2S(sb + SB_LO + c * BCH, gbl + c * BCH, BCH, mb);
            }
        }
        for (int c = 0; c < 8; c++) {
            MBARRIER_WAIT_PARITY(sb + S_MBAR + c * 8, kb & 1);
            consume_chunk(sb, c, l, mbase, nbase, acc);
        }
    }

    // epilogue
#pragma unroll
    for (int i = 0; i < 2; i++) {
        int row0 = bm + mbase + i * 16 + (l >> 2);
#pragma unroll
        for (int j = 0; j < 13; j++) {
            int col = nbase + j * 8 + (l & 3) * 2;
            if (col >= OD) continue;
            float bc0 = sbias[col], bc1 = sbias[col + 1];
            if (row0 < nnodes) {
                float2 v = make_float2(acc[i][j][0] + bc0, acc[i][j][1] + bc1);
                *(float2*)(out + ((size_t)s * nnodes + row0) * OD + col) = v;
            }
            int row1 = row0 + 8;
            if (row1 < nnodes) {
                float2 v = make_float2(acc[i][j][2] + bc0, acc[i][j][3] + bc1);
                *(float2*)(out + ((size_t)s * nnodes + row1) * OD + col) = v;
            }
        }
    }
}

static inline int cdiv(int a, int b) { return (a + b - 1) / b; }

extern "C" void kernel_launch(void* const* d_in, const int* in_sizes, int n_in,
                              void* d_out, int out_size) {
    const float* x    = (const float*)d_in[0];
    const int*   ei   = (const int*)  d_in[1];
    const float* ew   = (const float*)d_in[2];
    const float* w1_0 = (const float*)d_in[3];
    const float* b1   = (const float*)d_in[4];
    const float* w2_0 = (const float*)d_in[5];
    const float* w2_1 = (const float*)d_in[6];
    const float* b2   = (const float*)d_in[7];
    const float* w3_0 = (const float*)d_in[8];
    const float* w3_1 = (const float*)d_in[9];
    const float* w3_2 = (const float*)d_in[10];
    const float* b3   = (const float*)d_in[11];
    float* out = (float*)d_out;

    int E = in_sizes[2];
    int N = in_sizes[0] / FD;
    if (N > NN) N = NN;
    const int* src = ei;
    const int* dst = ei + E;

    static int smem_set = 0;
    if (!smem_set) {
        cudaFuncSetAttribute(gemm_kernel, cudaFuncAttributeMaxDynamicSharedMemorySize, S_TOTAL);
        smem_set = 1;
    }

    zero_kernel<<<cdiv(N, 256), 256>>>(N);
    deg_kernel<<<cdiv(E, 256), 256>>>(src, ew, E);
    fill_kernel<<<cdiv(E, 256), 256>>>(src, dst, ew, E);
    convert_x_kernel<<<cdiv(N * 32, 256), 256>>>((const float4*)x, N * 32);
    wprep_kernel<<<cdiv(6 * FD * BCOLS, 256), 256>>>(w1_0, w2_0, w2_1, w3_0, w3_1, w3_2);
    spmm_kernel<0><<<cdiv(N, 8), 256>>>(x, N);
    spmm_kernel<1><<<cdiv(N, 8), 256>>>(x, N);

    dim3 grid(NT, 3);
    gemm_kernel<<<grid, 256, S_TOTAL>>>(b1, b2, b3, out, N);
}

// round 6
// speedup vs baseline: 4.5362x; 1.2635x over previous
#include <cuda_runtime.h>
#include <cuda_fp16.h>
#include <cstdint>

// Problem constants: N=50000, E=800000, IN=128, OUT=200
#define NN   50000
#define FD   128
#define OD   200
#define CAP  96
#define MT   128
#define NT   391                   // M tiles
// A operand image (fp16): [tile][chunk ks 0..7][row 0..127][48B], 32B data + 16B pad
#define AROW   48
#define ACH    (128 * AROW)        // 6144 B per chunk
#define ATILE  (8 * ACH)           // 49152 B per tile
#define AELEMS ((size_t)NT * ATILE / 2)
// B (weight) image (fp16): [k 0..127][216 cols] row 432B; chunk = 16 rows = 6912B
#define BCOLS  216
#define BROW   (BCOLS * 2)         // 432
#define BCH    (16 * BROW)         // 6912
#define BELEMS ((size_t)FD * BCOLS)

// ================= device scratch (no cudaMalloc allowed) ================
__device__ float d_deg[NN];
__device__ int   d_cnt[NN];
__device__ int   d_bsrc[(size_t)NN * CAP];
__device__ float d_bnorm[(size_t)NN * CAP];
__device__ __align__(16)   float d_tx1[(size_t)NN * FD];
// chunk-major fp16 operand images of tx0(x), tx1, tx2 (zero-init covers pad rows)
__device__ __align__(1024) __half d_a[3][AELEMS];
// weights hi/lo fp16, order: w1_0, w2_0, w2_1, w3_0, w3_1, w3_2
__device__ __align__(1024) __half d_wh[6][BELEMS];
__device__ __align__(1024) __half d_wl[6][BELEMS];

// ================= helpers ==============================================
__device__ __forceinline__ uint32_t smem_u32(const void* p) {
    uint32_t a;
    asm("{ .reg .u64 t; cvta.to.shared.u64 t, %1; cvt.u32.u64 %0, t; }" : "=r"(a) : "l"(p));
    return a;
}
#define MBARRIER_INIT(mb, c) \
    asm volatile("mbarrier.init.shared.b64 [%0], %1;" :: "r"((uint32_t)(mb)), "r"((uint32_t)(c)) : "memory")
#define MBARRIER_EXPECT_TX(mb, tx) \
    asm volatile("mbarrier.arrive.expect_tx.shared.b64 _, [%0], %1;" :: "r"((uint32_t)(mb)), "r"((uint32_t)(tx)) : "memory")
#define BULK_G2S(dst, src, bytes, mb) \
    asm volatile("cp.async.bulk.shared::cta.global.mbarrier::complete_tx::bytes [%0], [%1], %2, [%3];" \
        :: "r"((uint32_t)(dst)), "l"(src), "r"((uint32_t)(bytes)), "r"((uint32_t)(mb)) : "memory")
#define MBARRIER_WAIT_PARITY(mb, ph) do {                                        \
    uint32_t _mb = (uint32_t)(mb), _ph = (uint32_t)(ph), _done;                  \
    asm volatile("{\n\t.reg .pred p;\n\t"                                        \
        "mbarrier.try_wait.parity.acquire.cta.shared::cta.b64 p, [%1], %2;\n\t"  \
        "selp.b32 %0, 1, 0, p;\n\t}" : "=r"(_done) : "r"(_mb), "r"(_ph) : "memory"); \
    if (!_done) {                                                                \
        asm volatile("{\n\t.reg .pred P1;\n\t"                                   \
            "W%=:\n\t"                                                           \
            "mbarrier.try_wait.parity.acquire.cta.shared::cta.b64 P1, [%0], %1, 0x989680;\n\t" \
            "@P1 bra.uni D%=;\n\t"                                               \
            "bra.uni W%=;\n\t"                                                   \
            "D%=:\n\t}" :: "r"(_mb), "r"(_ph) : "memory");                       \
    }                                                                            \
} while (0)

__device__ __forceinline__ void ldsm4(uint32_t* r, uint32_t addr) {
    asm volatile("ldmatrix.sync.aligned.m8n8.x4.shared.b16 {%0,%1,%2,%3}, [%4];"
                 : "=r"(r[0]), "=r"(r[1]), "=r"(r[2]), "=r"(r[3]) : "r"(addr));
}
__device__ __forceinline__ void ldsm4t(uint32_t* r, uint32_t addr) {
    asm volatile("ldmatrix.sync.aligned.m8n8.x4.trans.shared.b16 {%0,%1,%2,%3}, [%4];"
                 : "=r"(r[0]), "=r"(r[1]), "=r"(r[2]), "=r"(r[3]) : "r"(addr));
}
__device__ __forceinline__ void mma16816(float* c, const uint32_t* a, const uint32_t* b) {
    asm volatile("mma.sync.aligned.m16n8k16.row.col.f32.f16.f16.f32 "
                 "{%0,%1,%2,%3}, {%4,%5,%6,%7}, {%8,%9}, {%0,%1,%2,%3};"
                 : "+f"(c[0]), "+f"(c[1]), "+f"(c[2]), "+f"(c[3])
                 : "r"(a[0]), "r"(a[1]), "r"(a[2]), "r"(a[3]), "r"(b[0]), "r"(b[1]));
}

// ================= graph preprocessing ==================================
__global__ void deg_kernel(const int* __restrict__ src, const float* __restrict__ w, int E) {
    int e = blockIdx.x * blockDim.x + threadIdx.x;
    if (e < E) atomicAdd(&d_deg[src[e]], w[e]);
}
__global__ void fill_kernel(const int* __restrict__ src, const int* __restrict__ dst,
                            const float* __restrict__ w, int E) {
    int e = blockIdx.x * blockDim.x + threadIdx.x;
    if (e >= E) return;
    int s = src[e], d = dst[e];
    float ds = d_deg[s], dd = d_deg[d];
    float is = ds > 0.f ? rsqrtf(ds) : 0.f;
    float id = dd > 0.f ? rsqrtf(dd) : 0.f;
    float nrm = -is * w[e] * id;
    int slot = atomicAdd(&d_cnt[d], 1);
    if (slot < CAP) {
        d_bsrc[(size_t)d * CAP + slot]  = s;
        d_bnorm[(size_t)d * CAP + slot] = nrm;
    }
}

// store a float4 (features l*4..l*4+3 of one node row) into op's fp16 A image
__device__ __forceinline__ void store_a4(int op, int node, int l, float4 v) {
    int tile = node >> 7, r = node & 127, ks = l >> 2;
    size_t e = ((size_t)(tile * 8 + ks) * 128 + r) * 24 + (l & 3) * 4;
    __half2 p0 = __floats2half2_rn(v.x, v.y);
    __half2 p1 = __floats2half2_rn(v.z, v.w);
    *(uint2*)&d_a[op][e] = make_uint2(*(uint32_t*)&p0, *(uint32_t*)&p1);
}

// weights fp32 [k=128][n=200] -> fp16 hi/lo [k=128][n=216] zero padded
__global__ void wprep_kernel(const float* w0, const float* w1, const float* w2,
                             const float* w3, const float* w4, const float* w5) {
    const float* ws[6] = {w0, w1, w2, w3, w4, w5};
    int i = blockIdx.x * blockDim.x + threadIdx.x;
    if (i >= 6 * FD * BCOLS) return;
    int m = i / (FD * BCOLS);
    int r = i % (FD * BCOLS);
    int k = r / BCOLS, n = r % BCOLS;
    float v = (n < OD) ? ws[m][(size_t)k * OD + n] : 0.f;
    __half h = __float2half_rn(v);
    d_wh[m][r] = h;
    d_wl[m][r] = __float2half_rn(v - __half2float(h));
}

// gather SpMM, warp-per-node, float4 lanes.
// MODE 0: also emits x fp16 image (op0); writes tx1 fp32 + fp16 image (op1).
// MODE 1: tx2 = 2 L^ tx1 - x -> fp16 image (op2).
template <int MODE>
__global__ __launch_bounds__(256) void spmm_kernel(const float* __restrict__ x, int nnodes) {
    __shared__ int   ssrc[8][CAP];
    __shared__ float snrm[8][CAP];
    int w = threadIdx.x >> 5, l = threadIdx.x & 31;
    int node = blockIdx.x * 8 + w;
    if (node >= nnodes) return;

    int cnt = d_cnt[node];
    if (cnt > CAP) cnt = CAP;
    for (int j = l; j < cnt; j += 32) {
        ssrc[w][j] = d_bsrc[(size_t)node * CAP + j];
        snrm[w][j] = d_bnorm[(size_t)node * CAP + j];
    }
    __syncwarp();

    const float4* h4 = (MODE == 0) ? (const float4*)x : (const float4*)d_tx1;
    float4 acc = make_float4(0.f, 0.f, 0.f, 0.f);
    int j = 0;
    for (; j + 4 <= cnt; j += 4) {
        float4 v0 = h4[(size_t)ssrc[w][j+0] * 32 + l];
        float4 v1 = h4[(size_t)ssrc[w][j+1] * 32 + l];
        float4 v2 = h4[(size_t)ssrc[w][j+2] * 32 + l];
        float4 v3 = h4[(size_t)ssrc[w][j+3] * 32 + l];
        float n0 = snrm[w][j+0], n1 = snrm[w][j+1], n2 = snrm[w][j+2], n3 = snrm[w][j+3];
        acc.x += n0*v0.x + n1*v1.x + n2*v2.x + n3*v3.x;
        acc.y += n0*v0.y + n1*v1.y + n2*v2.y + n3*v3.y;
        acc.z += n0*v0.z + n1*v1.z + n2*v2.z + n3*v3.z;
        acc.w += n0*v0.w + n1*v1.w + n2*v2.w + n3*v3.w;
    }
    for (; j < cnt; j++) {
        float4 v = h4[(size_t)ssrc[w][j] * 32 + l];
        float n0 = snrm[w][j];
        acc.x += n0*v.x; acc.y += n0*v.y; acc.z += n0*v.z; acc.w += n0*v.w;
    }

    if (MODE == 0) {
        float4 xv = ((const float4*)x)[(size_t)node * 32 + l];
        store_a4(0, node, l, xv);
        ((float4*)d_tx1)[(size_t)node * 32 + l] = acc;
        store_a4(1, node, l, acc);
    } else {
        float4 xv = ((const float4*)x)[(size_t)node * 32 + l];
        float4 t = make_float4(2.f*acc.x - xv.x, 2.f*acc.y - xv.y,
                               2.f*acc.z - xv.z, 2.f*acc.w - xv.w);
        store_a4(2, node, l, t);
    }
}

// ================= bulk-copy mma.sync GEMM (fp16, 2-product) ============
#define SA     0
#define SB_HI  (8 * ACH)                   // 49152
#define SB_LO  (SB_HI + 8 * BCH)           // 104448
#define S_BIAS (SB_LO + 8 * BCH)           // 159744
#define S_MBAR (S_BIAS + 896)              // 160640
#define S_TOTAL (S_MBAR + 64)              // 160704

__device__ __forceinline__ void consume_chunk(uint32_t sb, int c, int l,
                                              int mbase, int nbase,
                                              float acc[2][13][4]) {
    uint32_t a[2][4], bb[14][2];
    uint32_t aBase = sb + SA + c * ACH;
#pragma unroll
    for (int i = 0; i < 2; i++)
        ldsm4(a[i], aBase + (mbase + i * 16 + (l & 15)) * AROW + (l >> 4) * 16);
    uint32_t bBase = sb + SB_HI + c * BCH + (l & 15) * BROW + (l >> 4) * 16;
#pragma unroll
    for (int j2 = 0; j2 < 7; j2++)
        ldsm4t(&bb[j2 * 2][0], bBase + (nbase + j2 * 16) * 2);
#pragma unroll
    for (int i = 0; i < 2; i++)
#pragma unroll
        for (int j = 0; j < 13; j++) mma16816(acc[i][j], a[i], bb[j]);
#pragma unroll
    for (int j2 = 0; j2 < 7; j2++)
        ldsm4t(&bb[j2 * 2][0], bBase + (SB_LO - SB_HI) + (nbase + j2 * 16) * 2);
#pragma unroll
    for (int i = 0; i < 2; i++)
#pragma unroll
        for (int j = 0; j < 13; j++) mma16816(acc[i][j], a[i], bb[j]);
}

__global__ __launch_bounds__(256, 1) void gemm_kernel(
    const float* __restrict__ b1, const float* __restrict__ b2, const float* __restrict__ b3,
    float* __restrict__ out, int nnodes)
{
    extern __shared__ char smem[];
    const uint32_t sb = smem_u32(smem);
    const int tid = threadIdx.x;
    const int l = tid & 31;
    const int wid = tid >> 5;
    const int s = blockIdx.y;
    const int tile = blockIdx.x;
    const int bm = tile * MT;
    const int Kb = s + 1;
    const int wbase = s * (s + 1) / 2;
    float* sbias = (float*)(smem + S_BIAS);

    const float* bp = (s == 0) ? b1 : (s == 1) ? b2 : b3;
    if (tid < OD) sbias[tid] = bp[tid];
    if (tid == 0) {
#pragma unroll
        for (int c = 0; c < 8; c++) MBARRIER_INIT(sb + S_MBAR + c * 8, 1);
    }
    __syncthreads();

    const int wm = wid >> 1, wn = wid & 1;
    const int mbase = wm * 32, nbase = wn * 104;

    float acc[2][13][4];
#pragma unroll
    for (int i = 0; i < 2; i++)
#pragma unroll
        for (int j = 0; j < 13; j++)
#pragma unroll
            for (int r = 0; r < 4; r++) acc[i][j][r] = 0.f;

    for (int kb = 0; kb < Kb; kb++) {
        if (kb) __syncthreads();           // prior chunk buffers fully consumed
        if (tid == 0) {
            const char* ga  = (const char*)d_a[kb] + (size_t)tile * ATILE;
            const char* gbh = (const char*)d_wh[wbase + kb];
            const char* gbl = (const char*)d_wl[wbase + kb];
#pragma unroll
            for (int c = 0; c < 8; c++) {
                uint32_t mb = sb + S_MBAR + c * 8;
                MBARRIER_EXPECT_TX(mb, ACH + 2 * BCH);
                BULK_G2S(sb + SA    + c * ACH, ga  + c * ACH, ACH, mb);
                BULK_G2S(sb + SB_HI + c * BCH, gbh + c * BCH, BCH, mb);
                BULK_G2S(sb + SB_LO + c * BCH, gbl + c * BCH, BCH, mb);
            }
        }
        for (int c = 0; c < 8; c++) {
            MBARRIER_WAIT_PARITY(sb + S_MBAR + c * 8, kb & 1);
            consume_chunk(sb, c, l, mbase, nbase, acc);
        }
    }

    // epilogue
#pragma unroll
    for (int i = 0; i < 2; i++) {
        int row0 = bm + mbase + i * 16 + (l >> 2);
#pragma unroll
        for (int j = 0; j < 13; j++) {
            int col = nbase + j * 8 + (l & 3) * 2;
            if (col >= OD) continue;
            float bc0 = sbias[col], bc1 = sbias[col + 1];
            if (row0 < nnodes) {
                float2 v = make_float2(acc[i][j][0] + bc0, acc[i][j][1] + bc1);
                *(float2*)(out + ((size_t)s * nnodes + row0) * OD + col) = v;
            }
            int row1 = row0 + 8;
            if (row1 < nnodes) {
                float2 v = make_float2(acc[i][j][2] + bc0, acc[i][j][3] + bc1);
                *(float2*)(out + ((size_t)s * nnodes + row1) * OD + col) = v;
            }
        }
    }
}

static inline int cdiv(int a, int b) { return (a + b - 1) / b; }

extern "C" void kernel_launch(void* const* d_in, const int* in_sizes, int n_in,
                              void* d_out, int out_size) {
    const float* x    = (const float*)d_in[0];
    const int*   ei   = (const int*)  d_in[1];
    const float* ew   = (const float*)d_in[2];
    const float* w1_0 = (const float*)d_in[3];
    const float* b1   = (const float*)d_in[4];
    const float* w2_0 = (const float*)d_in[5];
    const float* w2_1 = (const float*)d_in[6];
    const float* b2   = (const float*)d_in[7];
    const float* w3_0 = (const float*)d_in[8];
    const float* w3_1 = (const float*)d_in[9];
    const float* w3_2 = (const float*)d_in[10];
    const float* b3   = (const float*)d_in[11];
    float* out = (float*)d_out;

    int E = in_sizes[2];
    int N = in_sizes[0] / FD;
    if (N > NN) N = NN;
    const int* src = ei;
    const int* dst = ei + E;

    static void* p_deg = nullptr;
    static void* p_cnt = nullptr;
    if (!p_deg) {
        cudaFuncSetAttribute(gemm_kernel, cudaFuncAttributeMaxDynamicSharedMemorySize, S_TOTAL);
        cudaGetSymbolAddress(&p_deg, d_deg);
        cudaGetSymbolAddress(&p_cnt, d_cnt);
    }

    cudaMemsetAsync(p_deg, 0, sizeof(float) * NN);
    cudaMemsetAsync(p_cnt, 0, sizeof(int) * NN);
    deg_kernel<<<cdiv(E, 256), 256>>>(src, ew, E);
    fill_kernel<<<cdiv(E, 256), 256>>>(src, dst, ew, E);
    wprep_kernel<<<cdiv(6 * FD * BCOLS, 256), 256>>>(w1_0, w2_0, w2_1, w3_0, w3_1, w3_2);
    spmm_kernel<0><<<cdiv(N, 8), 256>>>(x, N);
    spmm_kernel<1><<<cdiv(N, 8), 256>>>(x, N);

    dim3 grid(NT, 3);
    gemm_kernel<<<grid, 256, S_TOTAL>>>(b1, b2, b3, out, N);
}

// round 9
// speedup vs baseline: 4.8674x; 1.0730x over previous
#include <cuda_runtime.h>
#include <cuda_fp16.h>
#include <cstdint>

// Problem constants: N=50000, E=800000, IN=128, OUT=200
#define NN   50000
#define FD   128
#define OD   200
#define CAP  96
#define MT   128
#define NT   391                   // M tiles
// A operand image (fp16): [tile][chunk ks 0..7][row 0..127][48B], 32B data + 16B pad
#define AROW   48
#define ACH    (128 * AROW)        // 6144 B per chunk
#define ATILE  (8 * ACH)           // 49152 B per tile
#define AELEMS ((size_t)NT * ATILE / 2)
// B (weight) image (fp16): [k 0..127][216 cols] row 432B; chunk = 16 rows = 6912B
#define BCOLS  216
#define BROW   (BCOLS * 2)         // 432
#define BCH    (16 * BROW)         // 6912
#define BELEMS ((size_t)FD * BCOLS)

// ================= device scratch (no cudaMalloc allowed) ================
__device__ float d_deg[NN];
__device__ int   d_cnt[NN];
__device__ int2  d_bkt[(size_t)NN * CAP];     // packed (src, norm-as-int)
__device__ __align__(16)   float d_tx1[(size_t)NN * FD];
// chunk-major fp16 operand images of tx0(x), tx1, tx2 (zero-init covers pad rows)
__device__ __align__(1024) __half d_a[3][AELEMS];
// weights hi/lo fp16, order: w1_0, w2_0, w2_1, w3_0, w3_1, w3_2
__device__ __align__(1024) __half d_wh[6][BELEMS];
__device__ __align__(1024) __half d_wl[6][BELEMS];

// ================= helpers ==============================================
__device__ __forceinline__ uint32_t smem_u32(const void* p) {
    uint32_t a;
    asm("{ .reg .u64 t; cvta.to.shared.u64 t, %1; cvt.u32.u64 %0, t; }" : "=r"(a) : "l"(p));
    return a;
}
#define MBARRIER_INIT(mb, c) \
    asm volatile("mbarrier.init.shared.b64 [%0], %1;" :: "r"((uint32_t)(mb)), "r"((uint32_t)(c)) : "memory")
#define MBARRIER_EXPECT_TX(mb, tx) \
    asm volatile("mbarrier.arrive.expect_tx.shared.b64 _, [%0], %1;" :: "r"((uint32_t)(mb)), "r"((uint32_t)(tx)) : "memory")
#define MBARRIER_ARRIVE(mb) \
    asm volatile("mbarrier.arrive.shared.b64 _, [%0];" :: "r"((uint32_t)(mb)) : "memory")
#define BULK_G2S(dst, src, bytes, mb) \
    asm volatile("cp.async.bulk.shared::cta.global.mbarrier::complete_tx::bytes [%0], [%1], %2, [%3];" \
        :: "r"((uint32_t)(dst)), "l"(src), "r"((uint32_t)(bytes)), "r"((uint32_t)(mb)) : "memory")
#define MBARRIER_WAIT_PARITY(mb, ph) do {                                        \
    uint32_t _mb = (uint32_t)(mb), _ph = (uint32_t)(ph), _done;                  \
    asm volatile("{\n\t.reg .pred p;\n\t"                                        \
        "mbarrier.try_wait.parity.acquire.cta.shared::cta.b64 p, [%1], %2;\n\t"  \
        "selp.b32 %0, 1, 0, p;\n\t}" : "=r"(_done) : "r"(_mb), "r"(_ph) : "memory"); \
    if (!_done) {                                                                \
        asm volatile("{\n\t.reg .pred P1;\n\t"                                   \
            "W%=:\n\t"                                                           \
            "mbarrier.try_wait.parity.acquire.cta.shared::cta.b64 P1, [%0], %1, 0x989680;\n\t" \
            "@P1 bra.uni D%=;\n\t"                                               \
            "bra.uni W%=;\n\t"                                                   \
            "D%=:\n\t}" :: "r"(_mb), "r"(_ph) : "memory");                       \
    }                                                                            \
} while (0)

__device__ __forceinline__ void ldsm4(uint32_t* r, uint32_t addr) {
    asm volatile("ldmatrix.sync.aligned.m8n8.x4.shared.b16 {%0,%1,%2,%3}, [%4];"
                 : "=r"(r[0]), "=r"(r[1]), "=r"(r[2]), "=r"(r[3]) : "r"(addr));
}
__device__ __forceinline__ void ldsm4t(uint32_t* r, uint32_t addr) {
    asm volatile("ldmatrix.sync.aligned.m8n8.x4.trans.shared.b16 {%0,%1,%2,%3}, [%4];"
                 : "=r"(r[0]), "=r"(r[1]), "=r"(r[2]), "=r"(r[3]) : "r"(addr));
}
__device__ __forceinline__ void mma16816(float* c, const uint32_t* a, const uint32_t* b) {
    asm volatile("mma.sync.aligned.m16n8k16.row.col.f32.f16.f16.f32 "
                 "{%0,%1,%2,%3}, {%4,%5,%6,%7}, {%8,%9}, {%0,%1,%2,%3};"
                 : "+f"(c[0]), "+f"(c[1]), "+f"(c[2]), "+f"(c[3])
                 : "r"(a[0]), "r"(a[1]), "r"(a[2]), "r"(a[3]), "r"(b[0]), "r"(b[1]));
}

// ================= graph preprocessing ==================================
__global__ void deg_kernel(const int* __restrict__ src, const float* __restrict__ w, int E) {
    int e = blockIdx.x * blockDim.x + threadIdx.x;
    if (e < E) atomicAdd(&d_deg[src[e]], w[e]);
}
__global__ void fill_kernel(const int* __restrict__ src, const int* __restrict__ dst,
                            const float* __restrict__ w, int E) {
    int e = blockIdx.x * blockDim.x + threadIdx.x;
    if (e >= E) return;
    int s = src[e], d = dst[e];
    float ds = d_deg[s], dd = d_deg[d];
    float is = ds > 0.f ? rsqrtf(ds) : 0.f;
    float id = dd > 0.f ? rsqrtf(dd) : 0.f;
    float nrm = -is * w[e] * id;
    int slot = atomicAdd(&d_cnt[d], 1);
    if (slot < CAP)
        d_bkt[(size_t)d * CAP + slot] = make_int2(s, __float_as_int(nrm));
}

// store a float4 (features l*4..l*4+3 of one node row) into op's fp16 A image
__device__ __forceinline__ void store_a4(int op, int node, int l, float4 v) {
    int tile = node >> 7, r = node & 127, ks = l >> 2;
    size_t e = ((size_t)(tile * 8 + ks) * 128 + r) * 24 + (l & 3) * 4;
    __half2 p0 = __floats2half2_rn(v.x, v.y);
    __half2 p1 = __floats2half2_rn(v.z, v.w);
    *(uint2*)&d_a[op][e] = make_uint2(*(uint32_t*)&p0, *(uint32_t*)&p1);
}

// weights fp32 [k=128][n=200] -> fp16 hi/lo [k=128][n=216] zero padded
__global__ void wprep_kernel(const float* w0, const float* w1, const float* w2,
                             const float* w3, const float* w4, const float* w5) {
    const float* ws[6] = {w0, w1, w2, w3, w4, w5};
    int i = blockIdx.x * blockDim.x + threadIdx.x;
    if (i >= 6 * FD * BCOLS) return;
    int m = i / (FD * BCOLS);
    int r = i % (FD * BCOLS);
    int k = r / BCOLS, n = r % BCOLS;
    float v = (n < OD) ? ws[m][(size_t)k * OD + n] : 0.f;
    __half h = __float2half_rn(v);
    d_wh[m][r] = h;
    d_wl[m][r] = __float2half_rn(v - __half2float(h));
}

// gather SpMM, warp-per-node, float4 lanes.
// MODE 0: also emits x fp16 image (op0); writes tx1 fp32 + fp16 image (op1).
// MODE 1: tx2 = 2 L^ tx1 - x -> fp16 image (op2).
template <int MODE>
__global__ __launch_bounds__(256) void spmm_kernel(const float* __restrict__ x, int nnodes) {
    __shared__ int   ssrc[8][CAP];
    __shared__ float snrm[8][CAP];
    int w = threadIdx.x >> 5, l = threadIdx.x & 31;
    int node = blockIdx.x * 8 + w;
    if (node >= nnodes) return;

    int cnt = d_cnt[node];
    if (cnt > CAP) cnt = CAP;
    for (int j = l; j < cnt; j += 32) {
        int2 b = d_bkt[(size_t)node * CAP + j];
        ssrc[w][j] = b.x;
        snrm[w][j] = __int_as_float(b.y);
    }
    __syncwarp();

    const float4* h4 = (MODE == 0) ? (const float4*)x : (const float4*)d_tx1;
    float4 acc = make_float4(0.f, 0.f, 0.f, 0.f);
    int j = 0;
    for (; j + 4 <= cnt; j += 4) {
        float4 v0 = h4[(size_t)ssrc[w][j+0] * 32 + l];
        float4 v1 = h4[(size_t)ssrc[w][j+1] * 32 + l];
        float4 v2 = h4[(size_t)ssrc[w][j+2] * 32 + l];
        float4 v3 = h4[(size_t)ssrc[w][j+3] * 32 + l];
        float n0 = snrm[w][j+0], n1 = snrm[w][j+1], n2 = snrm[w][j+2], n3 = snrm[w][j+3];
        acc.x += n0*v0.x + n1*v1.x + n2*v2.x + n3*v3.x;
        acc.y += n0*v0.y + n1*v1.y + n2*v2.y + n3*v3.y;
        acc.z += n0*v0.z + n1*v1.z + n2*v2.z + n3*v3.z;
        acc.w += n0*v0.w + n1*v1.w + n2*v2.w + n3*v3.w;
    }
    for (; j < cnt; j++) {
        float4 v = h4[(size_t)ssrc[w][j] * 32 + l];
        float n0 = snrm[w][j];
        acc.x += n0*v.x; acc.y += n0*v.y; acc.z += n0*v.z; acc.w += n0*v.w;
    }

    if (MODE == 0) {
        float4 xv = ((const float4*)x)[(size_t)node * 32 + l];
        store_a4(0, node, l, xv);
        ((float4*)d_tx1)[(size_t)node * 32 + l] = acc;
        store_a4(1, node, l, acc);
    } else {
        float4 xv = ((const float4*)x)[(size_t)node * 32 + l];
        float4 t = make_float4(2.f*acc.x - xv.x, 2.f*acc.y - xv.y,
                               2.f*acc.z - xv.z, 2.f*acc.w - xv.w);
        store_a4(2, node, l, t);
    }
}

// ================= ring-pipelined mma.sync GEMM (fp16, 2-product) =======
#define SA     0
#define SB_HI  (8 * ACH)                   // 49152
#define SB_LO  (SB_HI + 8 * BCH)           // 104448
#define S_BIAS (SB_LO + 8 * BCH)           // 159744
#define S_MBF  (S_BIAS + 896)              // full barriers, 8 x 8B
#define S_MBE  (S_MBF + 64)                // empty barriers, 8 x 8B
#define S_TOTAL (S_MBE + 64)               // 160768

__device__ __forceinline__ void consume_chunk(uint32_t sb, int c, int l,
                                              int mbase, int nbase,
                                              float acc[2][13][4]) {
    uint32_t a[2][4], bb[14][2];
    uint32_t aBase = sb + SA + c * ACH;
#pragma unroll
    for (int i = 0; i < 2; i++)
        ldsm4(a[i], aBase + (mbase + i * 16 + (l & 15)) * AROW + (l >> 4) * 16);
    uint32_t bBase = sb + SB_HI + c * BCH + (l & 15) * BROW + (l >> 4) * 16;
#pragma unroll
    for (int j2 = 0; j2 < 7; j2++)
        ldsm4t(&bb[j2 * 2][0], bBase + (nbase + j2 * 16) * 2);
#pragma unroll
    for (int i = 0; i < 2; i++)
#pragma unroll
        for (int j = 0; j < 13; j++) mma16816(acc[i][j], a[i], bb[j]);
#pragma unroll
    for (int j2 = 0; j2 < 7; j2++)
        ldsm4t(&bb[j2 * 2][0], bBase + (SB_LO - SB_HI) + (nbase + j2 * 16) * 2);
#pragma unroll
    for (int i = 0; i < 2; i++)
#pragma unroll
        for (int j = 0; j < 13; j++) mma16816(acc[i][j], a[i], bb[j]);
}

// issue the 3 bulk copies for global chunk index t into slot (t & 7); single lane
__device__ __forceinline__ void issue_chunk(uint32_t sb, int t, int tile, int wbase) {
    int kb = t >> 3, c = t & 7;
    int slot = t & 7;
    const char* ga  = (const char*)d_a[kb] + (size_t)tile * ATILE + c * ACH;
    const char* gbh = (const char*)d_wh[wbase + kb] + c * BCH;
    const char* gbl = (const char*)d_wl[wbase + kb] + c * BCH;
    uint32_t mb = sb + S_MBF + slot * 8;
    MBARRIER_EXPECT_TX(mb, ACH + 2 * BCH);
    BULK_G2S(sb + SA    + slot * ACH, ga,  ACH, mb);
    BULK_G2S(sb + SB_HI + slot * BCH, gbh, BCH, mb);
    BULK_G2S(sb + SB_LO + slot * BCH, gbl, BCH, mb);
}

__global__ __launch_bounds__(256, 1) void gemm_kernel(
    const float* __restrict__ b1, const float* __restrict__ b2, const float* __restrict__ b3,
    float* __restrict__ out, int nnodes)
{
    extern __shared__ char smem[];
    const uint32_t sb = smem_u32(smem);
    const int tid = threadIdx.x;
    const int l = tid & 31;
    const int wid = tid >> 5;
    const int s = blockIdx.y;
    const int tile = blockIdx.x;
    const int bm = tile * MT;
    const int T = 8 * (s + 1);           // total chunks
    const int wbase = s * (s + 1) / 2;
    float* sbias = (float*)(smem + S_BIAS);

    const float* bp = (s == 0) ? b1 : (s == 1) ? b2 : b3;
    if (tid < OD) sbias[tid] = bp[tid];
    if (tid == 0) {
#pragma unroll
        for (int c = 0; c < 8; c++) {
            MBARRIER_INIT(sb + S_MBF + c * 8, 1);   // full: tx-completed
            MBARRIER_INIT(sb + S_MBE + c * 8, 8);   // empty: one arrive per warp
        }
    }
    __syncthreads();

    // prologue: fill all 8 slots (single lane; non-blocking issues)
    if (tid == 0)
        for (int t = 0; t < 8; t++) issue_chunk(sb, t, tile, wbase);

    const int wm = wid >> 1, wn = wid & 1;
    const int mbase = wm * 32, nbase = wn * 104;

    float acc[2][13][4];
#pragma unroll
    for (int i = 0; i < 2; i++)
#pragma unroll
        for (int j = 0; j < 13; j++)
#pragma unroll
            for (int r = 0; r < 4; r++) acc[i][j][r] = 0.f;

    for (int t = 0; t < T; t++) {
        int slot = t & 7;
        int use  = t >> 3;
        MBARRIER_WAIT_PARITY(sb + S_MBF + slot * 8, use & 1);
        consume_chunk(sb, slot, l, mbase, nbase, acc);
        __syncwarp();
        if (l == 0) MBARRIER_ARRIVE(sb + S_MBE + slot * 8);
        // Producer: WHOLE warp 0 executes the blocking empty-wait (warp-uniform,
        // no divergent spin against the next collective); only lane 0 issues.
        if (wid == 0 && t + 8 < T) {
            MBARRIER_WAIT_PARITY(sb + S_MBE + slot * 8, use & 1);
            if (l == 0) issue_chunk(sb, t + 8, tile, wbase);
        }
        __syncwarp();
    }

    // epilogue
#pragma unroll
    for (int i = 0; i < 2; i++) {
        int row0 = bm + mbase + i * 16 + (l >> 2);
#pragma unroll
        for (int j = 0; j < 13; j++) {
            int col = nbase + j * 8 + (l & 3) * 2;
            if (col >= OD) continue;
            float bc0 = sbias[col], bc1 = sbias[col + 1];
            if (row0 < nnodes) {
                float2 v = make_float2(acc[i][j][0] + bc0, acc[i][j][1] + bc1);
                *(float2*)(out + ((size_t)s * nnodes + row0) * OD + col) = v;
            }
            int row1 = row0 + 8;
            if (row1 < nnodes) {
                float2 v = make_float2(acc[i][j][2] + bc0, acc[i][j][3] + bc1);
                *(float2*)(out + ((size_t)s * nnodes + row1) * OD + col) = v;
            }
        }
    }
}

static inline int cdiv(int a, int b) { return (a + b - 1) / b; }

extern "C" void kernel_launch(void* const* d_in, const int* in_sizes, int n_in,
                              void* d_out, int out_size) {
    const float* x    = (const float*)d_in[0];
    const int*   ei   = (const int*)  d_in[1];
    const float* ew   = (const float*)d_in[2];
    const float* w1_0 = (const float*)d_in[3];
    const float* b1   = (const float*)d_in[4];
    const float* w2_0 = (const float*)d_in[5];
    const float* w2_1 = (const float*)d_in[6];
    const float* b2   = (const float*)d_in[7];
    const float* w3_0 = (const float*)d_in[8];
    const float* w3_1 = (const float*)d_in[9];
    const float* w3_2 = (const float*)d_in[10];
    const float* b3   = (const float*)d_in[11];
    float* out = (float*)d_out;

    int E = in_sizes[2];
    int N = in_sizes[0] / FD;
    if (N > NN) N = NN;
    const int* src = ei;
    const int* dst = ei + E;

    static void* p_deg = nullptr;
    static void* p_cnt = nullptr;
    if (!p_deg) {
        cudaFuncSetAttribute(gemm_kernel, cudaFuncAttributeMaxDynamicSharedMemorySize, S_TOTAL);
        cudaGetSymbolAddress(&p_deg, d_deg);
        cudaGetSymbolAddress(&p_cnt, d_cnt);
    }

    cudaMemsetAsync(p_deg, 0, sizeof(float) * NN);
    cudaMemsetAsync(p_cnt, 0, sizeof(int) * NN);
    deg_kernel<<<cdiv(E, 256), 256>>>(src, ew, E);
    fill_kernel<<<cdiv(E, 256), 256>>>(src, dst, ew, E);
    wprep_kernel<<<cdiv(6 * FD * BCOLS, 256), 256>>>(w1_0, w2_0, w2_1, w3_0, w3_1, w3_2);
    spmm_kernel<0><<<cdiv(N, 8), 256>>>(x, N);
    spmm_kernel<1><<<cdiv(N, 8), 256>>>(x, N);

    dim3 grid(NT, 3);
    gemm_kernel<<<grid, 256, S_TOTAL>>>(b1, b2, b3, out, N);
}

// round 10
// speedup vs baseline: 5.5443x; 1.1391x over previous
#include <cuda_runtime.h>
#include <cuda_fp16.h>
#include <cstdint>

// Problem constants: N=50000, E=800000, IN=128, OUT=200
#define NN   50000
#define FD   128
#define OD   200
#define CAP  96
#define MT   128
#define NT   391                   // M tiles
// A operand image (fp16): [tile][chunk ks 0..7][row 0..127][48B], 32B data + 16B pad
#define AROW   48
#define ACH    (128 * AROW)        // 6144 B per chunk
#define ATILE  (8 * ACH)           // 49152 B per tile
#define AELEMS ((size_t)NT * ATILE / 2)
// B (weight) image (fp16): [k 0..127][216 cols] row 432B; chunk = 16 rows = 6912B
#define BCOLS  216
#define BROW   (BCOLS * 2)         // 432
#define BCH    (16 * BROW)         // 6912
#define BELEMS ((size_t)FD * BCOLS)

// ================= device scratch (no cudaMalloc allowed) ================
__device__ float d_deg[NN];
__device__ int   d_cnt[NN];
__device__ int2  d_bkt[(size_t)NN * CAP];     // packed (src, norm-as-int)
__device__ __align__(16)   float d_tx1[(size_t)NN * FD];
// chunk-major fp16 operand images of tx0(x), tx1, tx2 (zero-init covers pad rows)
__device__ __align__(1024) __half d_a[3][AELEMS];
// weights fp16, order: w1_0, w2_0, w2_1, w3_0, w3_1, w3_2
__device__ __align__(1024) __half d_wh[6][BELEMS];

// ================= helpers ==============================================
__device__ __forceinline__ uint32_t smem_u32(const void* p) {
    uint32_t a;
    asm("{ .reg .u64 t; cvta.to.shared.u64 t, %1; cvt.u32.u64 %0, t; }" : "=r"(a) : "l"(p));
    return a;
}
#define MBARRIER_INIT(mb, c) \
    asm volatile("mbarrier.init.shared.b64 [%0], %1;" :: "r"((uint32_t)(mb)), "r"((uint32_t)(c)) : "memory")
#define MBARRIER_EXPECT_TX(mb, tx) \
    asm volatile("mbarrier.arrive.expect_tx.shared.b64 _, [%0], %1;" :: "r"((uint32_t)(mb)), "r"((uint32_t)(tx)) : "memory")
#define MBARRIER_ARRIVE(mb) \
    asm volatile("mbarrier.arrive.shared.b64 _, [%0];" :: "r"((uint32_t)(mb)) : "memory")
#define BULK_G2S(dst, src, bytes, mb) \
    asm volatile("cp.async.bulk.shared::cta.global.mbarrier::complete_tx::bytes [%0], [%1], %2, [%3];" \
        :: "r"((uint32_t)(dst)), "l"(src), "r"((uint32_t)(bytes)), "r"((uint32_t)(mb)) : "memory")
#define MBARRIER_WAIT_PARITY(mb, ph) do {                                        \
    uint32_t _mb = (uint32_t)(mb), _ph = (uint32_t)(ph), _done;                  \
    asm volatile("{\n\t.reg .pred p;\n\t"                                        \
        "mbarrier.try_wait.parity.acquire.cta.shared::cta.b64 p, [%1], %2;\n\t"  \
        "selp.b32 %0, 1, 0, p;\n\t}" : "=r"(_done) : "r"(_mb), "r"(_ph) : "memory"); \
    if (!_done) {                                                                \
        asm volatile("{\n\t.reg .pred P1;\n\t"                                   \
            "W%=:\n\t"                                                           \
            "mbarrier.try_wait.parity.acquire.cta.shared::cta.b64 P1, [%0], %1, 0x989680;\n\t" \
            "@P1 bra.uni D%=;\n\t"                                               \
            "bra.uni W%=;\n\t"                                                   \
            "D%=:\n\t}" :: "r"(_mb), "r"(_ph) : "memory");                       \
    }                                                                            \
} while (0)

__device__ __forceinline__ void ldsm4(uint32_t* r, uint32_t addr) {
    asm volatile("ldmatrix.sync.aligned.m8n8.x4.shared.b16 {%0,%1,%2,%3}, [%4];"
                 : "=r"(r[0]), "=r"(r[1]), "=r"(r[2]), "=r"(r[3]) : "r"(addr));
}
__device__ __forceinline__ void ldsm4t(uint32_t* r, uint32_t addr) {
    asm volatile("ldmatrix.sync.aligned.m8n8.x4.trans.shared.b16 {%0,%1,%2,%3}, [%4];"
                 : "=r"(r[0]), "=r"(r[1]), "=r"(r[2]), "=r"(r[3]) : "r"(addr));
}
__device__ __forceinline__ void mma16816(float* c, const uint32_t* a, const uint32_t* b) {
    asm volatile("mma.sync.aligned.m16n8k16.row.col.f32.f16.f16.f32 "
                 "{%0,%1,%2,%3}, {%4,%5,%6,%7}, {%8,%9}, {%0,%1,%2,%3};"
                 : "+f"(c[0]), "+f"(c[1]), "+f"(c[2]), "+f"(c[3])
                 : "r"(a[0]), "r"(a[1]), "r"(a[2]), "r"(a[3]), "r"(b[0]), "r"(b[1]));
}

// ================= graph preprocessing ==================================
__global__ void deg_kernel(const int* __restrict__ src, const float* __restrict__ w, int E) {
    int e = blockIdx.x * blockDim.x + threadIdx.x;
    if (e < E) atomicAdd(&d_deg[src[e]], w[e]);
}
__global__ void fill_kernel(const int* __restrict__ src, const int* __restrict__ dst,
                            const float* __restrict__ w, int E) {
    int e = blockIdx.x * blockDim.x + threadIdx.x;
    if (e >= E) return;
    int s = src[e], d = dst[e];
    float ds = d_deg[s], dd = d_deg[d];
    float is = ds > 0.f ? rsqrtf(ds) : 0.f;
    float id = dd > 0.f ? rsqrtf(dd) : 0.f;
    float nrm = -is * w[e] * id;
    int slot = atomicAdd(&d_cnt[d], 1);
    if (slot < CAP)
        d_bkt[(size_t)d * CAP + slot] = make_int2(s, __float_as_int(nrm));
}

// store a float4 (features l*4..l*4+3 of one node row) into op's fp16 A image
__device__ __forceinline__ void store_a4(int op, int node, int l, float4 v) {
    int tile = node >> 7, r = node & 127, ks = l >> 2;
    size_t e = ((size_t)(tile * 8 + ks) * 128 + r) * 24 + (l & 3) * 4;
    __half2 p0 = __floats2half2_rn(v.x, v.y);
    __half2 p1 = __floats2half2_rn(v.z, v.w);
    *(uint2*)&d_a[op][e] = make_uint2(*(uint32_t*)&p0, *(uint32_t*)&p1);
}

// weights fp32 [k=128][n=200] -> fp16 [k=128][n=216] zero padded
__global__ void wprep_kernel(const float* w0, const float* w1, const float* w2,
                             const float* w3, const float* w4, const float* w5) {
    const float* ws[6] = {w0, w1, w2, w3, w4, w5};
    int i = blockIdx.x * blockDim.x + threadIdx.x;
    if (i >= 6 * FD * BCOLS) return;
    int m = i / (FD * BCOLS);
    int r = i % (FD * BCOLS);
    int k = r / BCOLS, n = r % BCOLS;
    float v = (n < OD) ? ws[m][(size_t)k * OD + n] : 0.f;
    d_wh[m][r] = __float2half_rn(v);
}

// gather SpMM, warp-per-node, float4 lanes.
// MODE 0: also emits x fp16 image (op0); writes tx1 fp32 + fp16 image (op1).
// MODE 1: tx2 = 2 L^ tx1 - x -> fp16 image (op2).
template <int MODE>
__global__ __launch_bounds__(256) void spmm_kernel(const float* __restrict__ x, int nnodes) {
    __shared__ int   ssrc[8][CAP];
    __shared__ float snrm[8][CAP];
    int w = threadIdx.x >> 5, l = threadIdx.x & 31;
    int node = blockIdx.x * 8 + w;
    if (node >= nnodes) return;

    int cnt = d_cnt[node];
    if (cnt > CAP) cnt = CAP;
    for (int j = l; j < cnt; j += 32) {
        int2 b = d_bkt[(size_t)node * CAP + j];
        ssrc[w][j] = b.x;
        snrm[w][j] = __int_as_float(b.y);
    }
    __syncwarp();

    const float4* h4 = (MODE == 0) ? (const float4*)x : (const float4*)d_tx1;
    float4 acc = make_float4(0.f, 0.f, 0.f, 0.f);
    int j = 0;
    for (; j + 4 <= cnt; j += 4) {
        float4 v0 = h4[(size_t)ssrc[w][j+0] * 32 + l];
        float4 v1 = h4[(size_t)ssrc[w][j+1] * 32 + l];
        float4 v2 = h4[(size_t)ssrc[w][j+2] * 32 + l];
        float4 v3 = h4[(size_t)ssrc[w][j+3] * 32 + l];
        float n0 = snrm[w][j+0], n1 = snrm[w][j+1], n2 = snrm[w][j+2], n3 = snrm[w][j+3];
        acc.x += n0*v0.x + n1*v1.x + n2*v2.x + n3*v3.x;
        acc.y += n0*v0.y + n1*v1.y + n2*v2.y + n3*v3.y;
        acc.z += n0*v0.z + n1*v1.z + n2*v2.z + n3*v3.z;
        acc.w += n0*v0.w + n1*v1.w + n2*v2.w + n3*v3.w;
    }
    for (; j < cnt; j++) {
        float4 v = h4[(size_t)ssrc[w][j] * 32 + l];
        float n0 = snrm[w][j];
        acc.x += n0*v.x; acc.y += n0*v.y; acc.z += n0*v.z; acc.w += n0*v.w;
    }

    if (MODE == 0) {
        float4 xv = ((const float4*)x)[(size_t)node * 32 + l];
        store_a4(0, node, l, xv);
        ((float4*)d_tx1)[(size_t)node * 32 + l] = acc;
        store_a4(1, node, l, acc);
    } else {
        float4 xv = ((const float4*)x)[(size_t)node * 32 + l];
        float4 t = make_float4(2.f*acc.x - xv.x, 2.f*acc.y - xv.y,
                               2.f*acc.z - xv.z, 2.f*acc.w - xv.w);
        store_a4(2, node, l, t);
    }
}

// ================= ring-pipelined mma.sync GEMM (fp16, 1-product) =======
#define SA     0
#define SB     (8 * ACH)                   // 49152
#define S_BIAS (SB + 8 * BCH)              // 104448
#define S_MBF  (S_BIAS + 896)              // full barriers, 8 x 8B
#define S_MBE  (S_MBF + 64)                // empty barriers, 8 x 8B
#define S_TOTAL (S_MBE + 64)               // 105472

__device__ __forceinline__ void consume_chunk(uint32_t sb, int c, int l,
                                              int mbase, int nbase,
                                              float acc[2][13][4]) {
    uint32_t a[2][4], bb[14][2];
    uint32_t aBase = sb + SA + c * ACH;
#pragma unroll
    for (int i = 0; i < 2; i++)
        ldsm4(a[i], aBase + (mbase + i * 16 + (l & 15)) * AROW + (l >> 4) * 16);
    uint32_t bBase = sb + SB + c * BCH + (l & 15) * BROW + (l >> 4) * 16;
#pragma unroll
    for (int j2 = 0; j2 < 7; j2++)
        ldsm4t(&bb[j2 * 2][0], bBase + (nbase + j2 * 16) * 2);
#pragma unroll
    for (int i = 0; i < 2; i++)
#pragma unroll
        for (int j = 0; j < 13; j++) mma16816(acc[i][j], a[i], bb[j]);
}

// issue the 2 bulk copies for global chunk index t into slot (t & 7); single lane
__device__ __forceinline__ void issue_chunk(uint32_t sb, int t, int tile, int wbase) {
    int kb = t >> 3, c = t & 7;
    int slot = t & 7;
    const char* ga  = (const char*)d_a[kb] + (size_t)tile * ATILE + c * ACH;
    const char* gb  = (const char*)d_wh[wbase + kb] + c * BCH;
    uint32_t mb = sb + S_MBF + slot * 8;
    MBARRIER_EXPECT_TX(mb, ACH + BCH);
    BULK_G2S(sb + SA + slot * ACH, ga, ACH, mb);
    BULK_G2S(sb + SB + slot * BCH, gb, BCH, mb);
}

__global__ __launch_bounds__(256, 1) void gemm_kernel(
    const float* __restrict__ b1, const float* __restrict__ b2, const float* __restrict__ b3,
    float* __restrict__ out, int nnodes)
{
    extern __shared__ char smem[];
    const uint32_t sb = smem_u32(smem);
    const int tid = threadIdx.x;
    const int l = tid & 31;
    const int wid = tid >> 5;
    const int s = blockIdx.y;
    const int tile = blockIdx.x;
    const int bm = tile * MT;
    const int T = 8 * (s + 1);           // total chunks
    const int wbase = s * (s + 1) / 2;
    float* sbias = (float*)(smem + S_BIAS);

    const float* bp = (s == 0) ? b1 : (s == 1) ? b2 : b3;
    if (tid < OD) sbias[tid] = bp[tid];
    if (tid == 0) {
#pragma unroll
        for (int c = 0; c < 8; c++) {
            MBARRIER_INIT(sb + S_MBF + c * 8, 1);   // full: tx-completed
            MBARRIER_INIT(sb + S_MBE + c * 8, 8);   // empty: one arrive per warp
        }
    }
    __syncthreads();

    // prologue: fill all 8 slots (single lane; non-blocking issues)
    if (tid == 0)
        for (int t = 0; t < 8; t++) issue_chunk(sb, t, tile, wbase);

    const int wm = wid >> 1, wn = wid & 1;
    const int mbase = wm * 32, nbase = wn * 104;

    float acc[2][13][4];
#pragma unroll
    for (int i = 0; i < 2; i++)
#pragma unroll
        for (int j = 0; j < 13; j++)
#pragma unroll
            for (int r = 0; r < 4; r++) acc[i][j][r] = 0.f;

    for (int t = 0; t < T; t++) {
        int slot = t & 7;
        int use  = t >> 3;
        MBARRIER_WAIT_PARITY(sb + S_MBF + slot * 8, use & 1);
        consume_chunk(sb, slot, l, mbase, nbase, acc);
        __syncwarp();
        if (l == 0) MBARRIER_ARRIVE(sb + S_MBE + slot * 8);
        // Producer: WHOLE warp 0 executes the blocking empty-wait (warp-uniform,
        // no divergent spin against the next collective); only lane 0 issues.
        if (wid == 0 && t + 8 < T) {
            MBARRIER_WAIT_PARITY(sb + S_MBE + slot * 8, use & 1);
            if (l == 0) issue_chunk(sb, t + 8, tile, wbase);
        }
        __syncwarp();
    }

    // epilogue
#pragma unroll
    for (int i = 0; i < 2; i++) {
        int row0 = bm + mbase + i * 16 + (l >> 2);
#pragma unroll
        for (int j = 0; j < 13; j++) {
            int col = nbase + j * 8 + (l & 3) * 2;
            if (col >= OD) continue;
            float bc0 = sbias[col], bc1 = sbias[col + 1];
            if (row0 < nnodes) {
                float2 v = make_float2(acc[i][j][0] + bc0, acc[i][j][1] + bc1);
                *(float2*)(out + ((size_t)s * nnodes + row0) * OD + col) = v;
            }
            int row1 = row0 + 8;
            if (row1 < nnodes) {
                float2 v = make_float2(acc[i][j][2] + bc0, acc[i][j][3] + bc1);
                *(float2*)(out + ((size_t)s * nnodes + row1) * OD + col) = v;
            }
        }
    }
}

static inline int cdiv(int a, int b) { return (a + b - 1) / b; }

extern "C" void kernel_launch(void* const* d_in, const int* in_sizes, int n_in,
                              void* d_out, int out_size) {
    const float* x    = (const float*)d_in[0];
    const int*   ei   = (const int*)  d_in[1];
    const float* ew   = (const float*)d_in[2];
    const float* w1_0 = (const float*)d_in[3];
    const float* b1   = (const float*)d_in[4];
    const float* w2_0 = (const float*)d_in[5];
    const float* w2_1 = (const float*)d_in[6];
    const float* b2   = (const float*)d_in[7];
    const float* w3_0 = (const float*)d_in[8];
    const float* w3_1 = (const float*)d_in[9];
    const float* w3_2 = (const float*)d_in[10];
    const float* b3   = (const float*)d_in[11];
    float* out = (float*)d_out;

    int E = in_sizes[2];
    int N = in_sizes[0] / FD;
    if (N > NN) N = NN;
    const int* src = ei;
    const int* dst = ei + E;

    static void* p_deg = nullptr;
    static void* p_cnt = nullptr;
    if (!p_deg) {
        cudaFuncSetAttribute(gemm_kernel, cudaFuncAttributeMaxDynamicSharedMemorySize, S_TOTAL);
        cudaGetSymbolAddress(&p_deg, d_deg);
        cudaGetSymbolAddress(&p_cnt, d_cnt);
    }

    cudaMemsetAsync(p_deg, 0, sizeof(float) * NN);
    cudaMemsetAsync(p_cnt, 0, sizeof(int) * NN);
    deg_kernel<<<cdiv(E, 256), 256>>>(src, ew, E);
    fill_kernel<<<cdiv(E, 256), 256>>>(src, dst, ew, E);
    wprep_kernel<<<cdiv(6 * FD * BCOLS, 256), 256>>>(w1_0, w2_0, w2_1, w3_0, w3_1, w3_2);
    spmm_kernel<0><<<cdiv(N, 8), 256>>>(x, N);
    spmm_kernel<1><<<cdiv(N, 8), 256>>>(x, N);

    dim3 grid(NT, 3);
    gemm_kernel<<<grid, 256, S_TOTAL>>>(b1, b2, b3, out, N);
}

// round 12
// speedup vs baseline: 5.9260x; 1.0688x over previous
#include <cuda_runtime.h>
#include <cuda_fp16.h>
#include <cstdint>

// Problem constants: N=50000, E=800000, IN=128, OUT=200
#define NN   50000
#define FD   128
#define OD   200
#define CAP  96
#define MT   128
#define NT   391                   // M tiles
// A operand image (fp16): [tile][chunk ks 0..7][row 0..127][48B], 32B data + 16B pad
#define AROW   48
#define ACH    (128 * AROW)        // 6144 B per chunk
#define ATILE  (8 * ACH)           // 49152 B per tile
#define AELEMS ((size_t)NT * ATILE / 2)
// B (weight) image (fp16): [k 0..127][216 cols] row 432B; chunk = 16 rows = 6912B
#define BCOLS  216
#define BROW   (BCOLS * 2)         // 432
#define BCH    (16 * BROW)         // 6912
#define BELEMS ((size_t)FD * BCOLS)

// ================= device scratch (no cudaMalloc allowed) ================
__device__ float d_deg[NN];
__device__ int   d_cnt[NN];
__device__ int2  d_bkt[(size_t)NN * CAP];     // packed (src, norm-as-int)
// row-major fp16 copies for gathers (256B per node row)
__device__ __align__(16) __half d_xh[(size_t)NN * FD];
__device__ __align__(16) __half d_t1h[(size_t)NN * FD];
// chunk-major fp16 operand images of tx0(x), tx1, tx2 (zero-init covers pad rows)
__device__ __align__(1024) __half d_a[3][AELEMS];
// weights fp16, order: w1_0, w2_0, w2_1, w3_0, w3_1, w3_2
__device__ __align__(1024) __half d_wh[6][BELEMS];

// ================= helpers ==============================================
__device__ __forceinline__ uint32_t smem_u32(const void* p) {
    uint32_t a;
    asm("{ .reg .u64 t; cvta.to.shared.u64 t, %1; cvt.u32.u64 %0, t; }" : "=r"(a) : "l"(p));
    return a;
}
#define MBARRIER_INIT(mb, c) \
    asm volatile("mbarrier.init.shared.b64 [%0], %1;" :: "r"((uint32_t)(mb)), "r"((uint32_t)(c)) : "memory")
#define MBARRIER_EXPECT_TX(mb, tx) \
    asm volatile("mbarrier.arrive.expect_tx.shared.b64 _, [%0], %1;" :: "r"((uint32_t)(mb)), "r"((uint32_t)(tx)) : "memory")
#define MBARRIER_ARRIVE(mb) \
    asm volatile("mbarrier.arrive.shared.b64 _, [%0];" :: "r"((uint32_t)(mb)) : "memory")
#define BULK_G2S(dst, src, bytes, mb) \
    asm volatile("cp.async.bulk.shared::cta.global.mbarrier::complete_tx::bytes [%0], [%1], %2, [%3];" \
        :: "r"((uint32_t)(dst)), "l"(src), "r"((uint32_t)(bytes)), "r"((uint32_t)(mb)) : "memory")
#define MBARRIER_WAIT_PARITY(mb, ph) do {                                        \
    uint32_t _mb = (uint32_t)(mb), _ph = (uint32_t)(ph), _done;                  \
    asm volatile("{\n\t.reg .pred p;\n\t"                                        \
        "mbarrier.try_wait.parity.acquire.cta.shared::cta.b64 p, [%1], %2;\n\t"  \
        "selp.b32 %0, 1, 0, p;\n\t}" : "=r"(_done) : "r"(_mb), "r"(_ph) : "memory"); \
    if (!_done) {                                                                \
        asm volatile("{\n\t.reg .pred P1;\n\t"                                   \
            "W%=:\n\t"                                                           \
            "mbarrier.try_wait.parity.acquire.cta.shared::cta.b64 P1, [%0], %1, 0x989680;\n\t" \
            "@P1 bra.uni D%=;\n\t"                                               \
            "bra.uni W%=;\n\t"                                                   \
            "D%=:\n\t}" :: "r"(_mb), "r"(_ph) : "memory");                       \
    }                                                                            \
} while (0)

__device__ __forceinline__ void ldsm4(uint32_t* r, uint32_t addr) {
    asm volatile("ldmatrix.sync.aligned.m8n8.x4.shared.b16 {%0,%1,%2,%3}, [%4];"
                 : "=r"(r[0]), "=r"(r[1]), "=r"(r[2]), "=r"(r[3]) : "r"(addr));
}
__device__ __forceinline__ void ldsm4t(uint32_t* r, uint32_t addr) {
    asm volatile("ldmatrix.sync.aligned.m8n8.x4.trans.shared.b16 {%0,%1,%2,%3}, [%4];"
                 : "=r"(r[0]), "=r"(r[1]), "=r"(r[2]), "=r"(r[3]) : "r"(addr));
}
__device__ __forceinline__ void mma16816(float* c, const uint32_t* a, const uint32_t* b) {
    asm volatile("mma.sync.aligned.m16n8k16.row.col.f32.f16.f16.f32 "
                 "{%0,%1,%2,%3}, {%4,%5,%6,%7}, {%8,%9}, {%0,%1,%2,%3};"
                 : "+f"(c[0]), "+f"(c[1]), "+f"(c[2]), "+f"(c[3])
                 : "r"(a[0]), "r"(a[1]), "r"(a[2]), "r"(a[3]), "r"(b[0]), "r"(b[1]));
}

// ================= graph preprocessing ==================================
__global__ void deg_kernel(const int* __restrict__ src, const float* __restrict__ w, int E) {
    int e = blockIdx.x * blockDim.x + threadIdx.x;
    if (e < E) atomicAdd(&d_deg[src[e]], w[e]);
}
__global__ void fill_kernel(const int* __restrict__ src, const int* __restrict__ dst,
                            const float* __restrict__ w, int E) {
    int e = blockIdx.x * blockDim.x + threadIdx.x;
    if (e >= E) return;
    int s = src[e], d = dst[e];
    float ds = d_deg[s], dd = d_deg[d];
    float is = ds > 0.f ? rsqrtf(ds) : 0.f;
    float id = dd > 0.f ? rsqrtf(dd) : 0.f;
    float nrm = -is * w[e] * id;
    int slot = atomicAdd(&d_cnt[d], 1);
    if (slot < CAP)
        d_bkt[(size_t)d * CAP + slot] = make_int2(s, __float_as_int(nrm));
}

// pack a float4 to fp16 uint2
__device__ __forceinline__ uint2 pack_h4(float4 v) {
    __half2 p0 = __floats2half2_rn(v.x, v.y);
    __half2 p1 = __floats2half2_rn(v.z, v.w);
    return make_uint2(*(uint32_t*)&p0, *(uint32_t*)&p1);
}
// store a float4 (features l*4..l*4+3 of one node row) into op's fp16 A image
__device__ __forceinline__ void store_a4(int op, int node, int l, float4 v) {
    int tile = node >> 7, r = node & 127, ks = l >> 2;
    size_t e = ((size_t)(tile * 8 + ks) * 128 + r) * 24 + (l & 3) * 4;
    *(uint2*)&d_a[op][e] = pack_h4(v);
}
// unpack uint2 (4 fp16) -> float4
__device__ __forceinline__ float4 unpack_h4(uint2 u) {
    float2 f0 = __half22float2(*(__half2*)&u.x);
    float2 f1 = __half22float2(*(__half2*)&u.y);
    return make_float4(f0.x, f0.y, f1.x, f1.y);
}

// x fp32 -> x_h row-major fp16 + A image op0
__global__ void convert_x_kernel(const float4* __restrict__ x4, int nwords) {
    int i = blockIdx.x * blockDim.x + threadIdx.x;
    if (i >= nwords) return;
    int node = i >> 5, l = i & 31;
    float4 v = x4[i];
    ((uint2*)d_xh)[i] = pack_h4(v);
    store_a4(0, node, l, v);
}

// weights fp32 [k=128][n=200] -> fp16 [k=128][n=216] zero padded
__global__ void wprep_kernel(const float* w0, const float* w1, const float* w2,
                             const float* w3, const float* w4, const float* w5) {
    const float* ws[6] = {w0, w1, w2, w3, w4, w5};
    int i = blockIdx.x * blockDim.x + threadIdx.x;
    if (i >= 6 * FD * BCOLS) return;
    int m = i / (FD * BCOLS);
    int r = i % (FD * BCOLS);
    int k = r / BCOLS, n = r % BCOLS;
    float v = (n < OD) ? ws[m][(size_t)k * OD + n] : 0.f;
    d_wh[m][r] = __float2half_rn(v);
}

// gather SpMM (fp16 gather, fp32 accumulate), warp-per-node, 4 features/lane.
// MODE 0: tx1 = L^x    -> t1h row-major + A image op1   (gathers d_xh)
// MODE 1: tx2 = 2 L^ tx1 - x -> A image op2             (gathers d_t1h)
template <int MODE>
__global__ __launch_bounds__(256) void spmm_kernel(const float* __restrict__ x, int nnodes) {
    __shared__ int   ssrc[8][CAP];
    __shared__ float snrm[8][CAP];
    int w = threadIdx.x >> 5, l = threadIdx.x & 31;
    int node = blockIdx.x * 8 + w;
    if (node >= nnodes) return;

    int cnt = d_cnt[node];
    if (cnt > CAP) cnt = CAP;
    for (int j = l; j < cnt; j += 32) {
        int2 b = d_bkt[(size_t)node * CAP + j];
        ssrc[w][j] = b.x;
        snrm[w][j] = __int_as_float(b.y);
    }
    __syncwarp();

    const uint2* g = (MODE == 0) ? (const uint2*)d_xh : (const uint2*)d_t1h;
    float4 acc = make_float4(0.f, 0.f, 0.f, 0.f);
    int j = 0;
    for (; j + 4 <= cnt; j += 4) {
        float4 v0 = unpack_h4(g[(size_t)ssrc[w][j+0] * 32 + l]);
        float4 v1 = unpack_h4(g[(size_t)ssrc[w][j+1] * 32 + l]);
        float4 v2 = unpack_h4(g[(size_t)ssrc[w][j+2] * 32 + l]);
        float4 v3 = unpack_h4(g[(size_t)ssrc[w][j+3] * 32 + l]);
        float n0 = snrm[w][j+0], n1 = snrm[w][j+1], n2 = snrm[w][j+2], n3 = snrm[w][j+3];
        acc.x += n0*v0.x + n1*v1.x + n2*v2.x + n3*v3.x;
        acc.y += n0*v0.y + n1*v1.y + n2*v2.y + n3*v3.y;
        acc.z += n0*v0.z + n1*v1.z + n2*v2.z + n3*v3.z;
        acc.w += n0*v0.w + n1*v1.w + n2*v2.w + n3*v3.w;
    }
    for (; j < cnt; j++) {
        float4 v = unpack_h4(g[(size_t)ssrc[w][j] * 32 + l]);
        float n0 = snrm[w][j];
        acc.x += n0*v.x; acc.y += n0*v.y; acc.z += n0*v.z; acc.w += n0*v.w;
    }

    if (MODE == 0) {
        ((uint2*)d_t1h)[(size_t)node * 32 + l] = pack_h4(acc);
        store_a4(1, node, l, acc);
    } else {
        float4 xv = ((const float4*)x)[(size_t)node * 32 + l];
        float4 t = make_float4(2.f*acc.x - xv.x, 2.f*acc.y - xv.y,
                               2.f*acc.z - xv.z, 2.f*acc.w - xv.w);
        store_a4(2, node, l, t);
    }
}

// ================= ring-pipelined mma.sync GEMM (fp16, 1-product) =======
#define SA     0
#define SB     (8 * ACH)                   // 49152
#define S_BIAS (SB + 8 * BCH)              // 104448
#define S_MBF  (S_BIAS + 896)              // full barriers, 8 x 8B
#define S_MBE  (S_MBF + 64)                // empty barriers, 8 x 8B
#define S_TOTAL (S_MBE + 64)               // 105472

__device__ __forceinline__ void consume_chunk(uint32_t sb, int c, int l,
                                              int mbase, int nbase,
                                              float acc[2][13][4]) {
    uint32_t a[2][4], bb[14][2];
    uint32_t aBase = sb + SA + c * ACH;
#pragma unroll
    for (int i = 0; i < 2; i++)
        ldsm4(a[i], aBase + (mbase + i * 16 + (l & 15)) * AROW + (l >> 4) * 16);
    uint32_t bBase = sb + SB + c * BCH + (l & 15) * BROW + (l >> 4) * 16;
#pragma unroll
    for (int j2 = 0; j2 < 7; j2++)
        ldsm4t(&bb[j2 * 2][0], bBase + (nbase + j2 * 16) * 2);
#pragma unroll
    for (int i = 0; i < 2; i++)
#pragma unroll
        for (int j = 0; j < 13; j++) mma16816(acc[i][j], a[i], bb[j]);
}

// issue the 2 bulk copies for global chunk index t into slot (t & 7); single lane
__device__ __forceinline__ void issue_chunk(uint32_t sb, int t, int tile, int wbase) {
    int kb = t >> 3, c = t & 7;
    int slot = t & 7;
    const char* ga  = (const char*)d_a[kb] + (size_t)tile * ATILE + c * ACH;
    const char* gb  = (const char*)d_wh[wbase + kb] + c * BCH;
    uint32_t mb = sb + S_MBF + slot * 8;
    MBARRIER_EXPECT_TX(mb, ACH + BCH);
    BULK_G2S(sb + SA + slot * ACH, ga, ACH, mb);
    BULK_G2S(sb + SB + slot * BCH, gb, BCH, mb);
}

__global__ __launch_bounds__(256, 1) void gemm_kernel(
    const float* __restrict__ b1, const float* __restrict__ b2, const float* __restrict__ b3,
    float* __restrict__ out, int nnodes)
{
    extern __shared__ char smem[];
    const uint32_t sb = smem_u32(smem);
    const int tid = threadIdx.x;
    const int l = tid & 31;
    const int wid = tid >> 5;
    const int s = blockIdx.y;
    const int tile = blockIdx.x;
    const int bm = tile * MT;
    const int T = 8 * (s + 1);           // total chunks
    const int wbase = s * (s + 1) / 2;
    float* sbias = (float*)(smem + S_BIAS);

    const float* bp = (s == 0) ? b1 : (s == 1) ? b2 : b3;
    if (tid < OD) sbias[tid] = bp[tid];
    if (tid == 0) {
#pragma unroll
        for (int c = 0; c < 8; c++) {
            MBARRIER_INIT(sb + S_MBF + c * 8, 1);   // full: tx-completed
            MBARRIER_INIT(sb + S_MBE + c * 8, 8);   // empty: one arrive per warp
        }
    }
    __syncthreads();

    // prologue: fill all 8 slots (single lane; non-blocking issues)
    if (tid == 0)
        for (int t = 0; t < 8; t++) issue_chunk(sb, t, tile, wbase);

    const int wm = wid >> 1, wn = wid & 1;
    const int mbase = wm * 32, nbase = wn * 104;

    float acc[2][13][4];
#pragma unroll
    for (int i = 0; i < 2; i++)
#pragma unroll
        for (int j = 0; j < 13; j++)
#pragma unroll
            for (int r = 0; r < 4; r++) acc[i][j][r] = 0.f;

    for (int t = 0; t < T; t++) {
        int slot = t & 7;
        int use  = t >> 3;
        MBARRIER_WAIT_PARITY(sb + S_MBF + slot * 8, use & 1);
        consume_chunk(sb, slot, l, mbase, nbase, acc);
        __syncwarp();
        if (l == 0) MBARRIER_ARRIVE(sb + S_MBE + slot * 8);
        // Producer: WHOLE warp 0 executes the blocking empty-wait (warp-uniform,
        // no divergent spin against the next collective); only lane 0 issues.
        if (wid == 0 && t + 8 < T) {
            MBARRIER_WAIT_PARITY(sb + S_MBE + slot * 8, use & 1);
            if (l == 0) issue_chunk(sb, t + 8, tile, wbase);
        }
        __syncwarp();
    }

    // epilogue
#pragma unroll
    for (int i = 0; i < 2; i++) {
        int row0 = bm + mbase + i * 16 + (l >> 2);
#pragma unroll
        for (int j = 0; j < 13; j++) {
            int col = nbase + j * 8 + (l & 3) * 2;
            if (col >= OD) continue;
            float bc0 = sbias[col], bc1 = sbias[col + 1];
            if (row0 < nnodes) {
                float2 v = make_float2(acc[i][j][0] + bc0, acc[i][j][1] + bc1);
                *(float2*)(out + ((size_t)s * nnodes + row0) * OD + col) = v;
            }
            int row1 = row0 + 8;
            if (row1 < nnodes) {
                float2 v = make_float2(acc[i][j][2] + bc0, acc[i][j][3] + bc1);
                *(float2*)(out + ((size_t)s * nnodes + row1) * OD + col) = v;
            }
        }
    }
}

static inline int cdiv(int a, int b) { return (a + b - 1) / b; }

extern "C" void kernel_launch(void* const* d_in, const int* in_sizes, int n_in,
                              void* d_out, int out_size) {
    const float* x    = (const float*)d_in[0];
    const int*   ei   = (const int*)  d_in[1];
    const float* ew   = (const float*)d_in[2];
    const float* w1_0 = (const float*)d_in[3];
    const float* b1   = (const float*)d_in[4];
    const float* w2_0 = (const float*)d_in[5];
    const float* w2_1 = (const float*)d_in[6];
    const float* b2   = (const float*)d_in[7];
    const float* w3_0 = (const float*)d_in[8];
    const float* w3_1 = (const float*)d_in[9];
    const float* w3_2 = (const float*)d_in[10];
    const float* b3   = (const float*)d_in[11];
    float* out = (float*)d_out;

    int E = in_sizes[2];
    int N = in_sizes[0] / FD;
    if (N > NN) N = NN;
    const int* src = ei;
    const int* dst = ei + E;

    static void* p_deg = nullptr;
    static void* p_cnt = nullptr;
    if (!p_deg) {
        cudaFuncSetAttribute(gemm_kernel, cudaFuncAttributeMaxDynamicSharedMemorySize, S_TOTAL);
        cudaGetSymbolAddress(&p_deg, d_deg);
        cudaGetSymbolAddress(&p_cnt, d_cnt);
    }

    cudaMemsetAsync(p_deg, 0, sizeof(float) * NN);
    cudaMemsetAsync(p_cnt, 0, sizeof(int) * NN);
    deg_kernel<<<cdiv(E, 256), 256>>>(src, ew, E);
    fill_kernel<<<cdiv(E, 256), 256>>>(src, dst, ew, E);
    convert_x_kernel<<<cdiv(N * 32, 256), 256>>>((const float4*)x, N * 32);
    wprep_kernel<<<cdiv(6 * FD * BCOLS, 256), 256>>>(w1_0, w2_0, w2_1, w3_0, w3_1, w3_2);
    spmm_kernel<0><<<cdiv(N, 8), 256>>>(x, N);
    spmm_kernel<1><<<cdiv(N, 8), 256>>>(x, N);

    dim3 grid(NT, 3);
    gemm_kernel<<<grid, 256, S_TOTAL>>>(b1, b2, b3, out, N);
}

// round 13
// speedup vs baseline: 5.9803x; 1.0092x over previous
#include <cuda_runtime.h>
#include <cuda_fp16.h>
#include <cstdint>

// Problem constants: N=50000, E=800000, IN=128, OUT=200
#define NN   50000
#define FD   128
#define OD   200
#define CAP  96
#define MT   64
#define NT   782                   // M tiles (64 rows each), 782*64 = 50048
// A operand image (fp16): [tile][chunk ks 0..7][row 0..63][48B], 32B data + 16B pad
#define AROW   48
#define ACH    (MT * AROW)         // 3072 B per chunk
#define ATILE  (8 * ACH)           // 24576 B per tile
#define AELEMS ((size_t)NT * ATILE / 2)
// B (weight) image (fp16): [k 0..127][216 cols] row 432B; chunk = 16 rows = 6912B
#define BCOLS  216
#define BROW   (BCOLS * 2)         // 432
#define BCH    (16 * BROW)         // 6912
#define BELEMS ((size_t)FD * BCOLS)

// ================= device scratch (no cudaMalloc allowed) ================
__device__ float d_deg[NN];
__device__ int   d_cnt[NN];
__device__ int2  d_bkt[(size_t)NN * CAP];     // packed (src, norm-as-int)
// row-major fp16 copies for gathers (256B per node row)
__device__ __align__(16) __half d_xh[(size_t)NN * FD];
__device__ __align__(16) __half d_t1h[(size_t)NN * FD];
// chunk-major fp16 operand images of tx0(x), tx1, tx2 (zero-init covers pad rows)
__device__ __align__(1024) __half d_a[3][AELEMS];
// weights fp16, order: w1_0, w2_0, w2_1, w3_0, w3_1, w3_2
__device__ __align__(1024) __half d_wh[6][BELEMS];

// ================= helpers ==============================================
__device__ __forceinline__ uint32_t smem_u32(const void* p) {
    uint32_t a;
    asm("{ .reg .u64 t; cvta.to.shared.u64 t, %1; cvt.u32.u64 %0, t; }" : "=r"(a) : "l"(p));
    return a;
}
#define MBARRIER_INIT(mb, c) \
    asm volatile("mbarrier.init.shared.b64 [%0], %1;" :: "r"((uint32_t)(mb)), "r"((uint32_t)(c)) : "memory")
#define MBARRIER_EXPECT_TX(mb, tx) \
    asm volatile("mbarrier.arrive.expect_tx.shared.b64 _, [%0], %1;" :: "r"((uint32_t)(mb)), "r"((uint32_t)(tx)) : "memory")
#define MBARRIER_ARRIVE(mb) \
    asm volatile("mbarrier.arrive.shared.b64 _, [%0];" :: "r"((uint32_t)(mb)) : "memory")
#define BULK_G2S(dst, src, bytes, mb) \
    asm volatile("cp.async.bulk.shared::cta.global.mbarrier::complete_tx::bytes [%0], [%1], %2, [%3];" \
        :: "r"((uint32_t)(dst)), "l"(src), "r"((uint32_t)(bytes)), "r"((uint32_t)(mb)) : "memory")
#define MBARRIER_WAIT_PARITY(mb, ph) do {                                        \
    uint32_t _mb = (uint32_t)(mb), _ph = (uint32_t)(ph), _done;                  \
    asm volatile("{\n\t.reg .pred p;\n\t"                                        \
        "mbarrier.try_wait.parity.acquire.cta.shared::cta.b64 p, [%1], %2;\n\t"  \
        "selp.b32 %0, 1, 0, p;\n\t}" : "=r"(_done) : "r"(_mb), "r"(_ph) : "memory"); \
    if (!_done) {                                                                \
        asm volatile("{\n\t.reg .pred P1;\n\t"                                   \
            "W%=:\n\t"                                                           \
            "mbarrier.try_wait.parity.acquire.cta.shared::cta.b64 P1, [%0], %1, 0x989680;\n\t" \
            "@P1 bra.uni D%=;\n\t"                                               \
            "bra.uni W%=;\n\t"                                                   \
            "D%=:\n\t}" :: "r"(_mb), "r"(_ph) : "memory");                       \
    }                                                                            \
} while (0)

__device__ __forceinline__ void ldsm4(uint32_t* r, uint32_t addr) {
    asm volatile("ldmatrix.sync.aligned.m8n8.x4.shared.b16 {%0,%1,%2,%3}, [%4];"
                 : "=r"(r[0]), "=r"(r[1]), "=r"(r[2]), "=r"(r[3]) : "r"(addr));
}
__device__ __forceinline__ void ldsm4t(uint32_t* r, uint32_t addr) {
    asm volatile("ldmatrix.sync.aligned.m8n8.x4.trans.shared.b16 {%0,%1,%2,%3}, [%4];"
                 : "=r"(r[0]), "=r"(r[1]), "=r"(r[2]), "=r"(r[3]) : "r"(addr));
}
__device__ __forceinline__ void mma16816(float* c, const uint32_t* a, const uint32_t* b) {
    asm volatile("mma.sync.aligned.m16n8k16.row.col.f32.f16.f16.f32 "
                 "{%0,%1,%2,%3}, {%4,%5,%6,%7}, {%8,%9}, {%0,%1,%2,%3};"
                 : "+f"(c[0]), "+f"(c[1]), "+f"(c[2]), "+f"(c[3])
                 : "r"(a[0]), "r"(a[1]), "r"(a[2]), "r"(a[3]), "r"(b[0]), "r"(b[1]));
}

// ================= graph preprocessing ==================================
__global__ void deg_kernel(const int* __restrict__ src, const float* __restrict__ w, int E) {
    int e = blockIdx.x * blockDim.x + threadIdx.x;
    if (e < E) atomicAdd(&d_deg[src[e]], w[e]);
}
__global__ void fill_kernel(const int* __restrict__ src, const int* __restrict__ dst,
                            const float* __restrict__ w, int E) {
    int e = blockIdx.x * blockDim.x + threadIdx.x;
    if (e >= E) return;
    int s = src[e], d = dst[e];
    float ds = d_deg[s], dd = d_deg[d];
    float is = ds > 0.f ? rsqrtf(ds) : 0.f;
    float id = dd > 0.f ? rsqrtf(dd) : 0.f;
    float nrm = -is * w[e] * id;
    int slot = atomicAdd(&d_cnt[d], 1);
    if (slot < CAP)
        d_bkt[(size_t)d * CAP + slot] = make_int2(s, __float_as_int(nrm));
}

// pack a float4 to fp16 uint2
__device__ __forceinline__ uint2 pack_h4(float4 v) {
    __half2 p0 = __floats2half2_rn(v.x, v.y);
    __half2 p1 = __floats2half2_rn(v.z, v.w);
    return make_uint2(*(uint32_t*)&p0, *(uint32_t*)&p1);
}
// store a float4 (features l*4..l*4+3 of one node row) into op's fp16 A image
__device__ __forceinline__ void store_a4(int op, int node, int l, float4 v) {
    int tile = node >> 6, r = node & 63, ks = l >> 2;
    size_t e = ((size_t)(tile * 8 + ks) * MT + r) * 24 + (l & 3) * 4;
    *(uint2*)&d_a[op][e] = pack_h4(v);
}
// unpack uint2 (4 fp16) -> float4
__device__ __forceinline__ float4 unpack_h4(uint2 u) {
    float2 f0 = __half22float2(*(__half2*)&u.x);
    float2 f1 = __half22float2(*(__half2*)&u.y);
    return make_float4(f0.x, f0.y, f1.x, f1.y);
}

// x fp32 -> x_h row-major fp16 + A image op0
__global__ void convert_x_kernel(const float4* __restrict__ x4, int nwords) {
    int i = blockIdx.x * blockDim.x + threadIdx.x;
    if (i >= nwords) return;
    int node = i >> 5, l = i & 31;
    float4 v = x4[i];
    ((uint2*)d_xh)[i] = pack_h4(v);
    store_a4(0, node, l, v);
}

// weights fp32 [k=128][n=200] -> fp16 [k=128][n=216] zero padded
__global__ void wprep_kernel(const float* w0, const float* w1, const float* w2,
                             const float* w3, const float* w4, const float* w5) {
    const float* ws[6] = {w0, w1, w2, w3, w4, w5};
    int i = blockIdx.x * blockDim.x + threadIdx.x;
    if (i >= 6 * FD * BCOLS) return;
    int m = i / (FD * BCOLS);
    int r = i % (FD * BCOLS);
    int k = r / BCOLS, n = r % BCOLS;
    float v = (n < OD) ? ws[m][(size_t)k * OD + n] : 0.f;
    d_wh[m][r] = __float2half_rn(v);
}

// gather SpMM (fp16 gather, fp32 accumulate), warp-per-node, 4 features/lane, MLP=8.
// MODE 0: tx1 = L^x    -> t1h row-major + A image op1   (gathers d_xh)
// MODE 1: tx2 = 2 L^ tx1 - x -> A image op2             (gathers d_t1h)
template <int MODE>
__global__ __launch_bounds__(256) void spmm_kernel(const float* __restrict__ x, int nnodes) {
    __shared__ int   ssrc[8][CAP];
    __shared__ float snrm[8][CAP];
    int w = threadIdx.x >> 5, l = threadIdx.x & 31;
    int node = blockIdx.x * 8 + w;
    if (node >= nnodes) return;

    int cnt = d_cnt[node];
    if (cnt > CAP) cnt = CAP;
    for (int j = l; j < cnt; j += 32) {
        int2 b = d_bkt[(size_t)node * CAP + j];
        ssrc[w][j] = b.x;
        snrm[w][j] = __int_as_float(b.y);
    }
    __syncwarp();

    const uint2* g = (MODE == 0) ? (const uint2*)d_xh : (const uint2*)d_t1h;
    float4 acc = make_float4(0.f, 0.f, 0.f, 0.f);
    int j = 0;
    for (; j + 8 <= cnt; j += 8) {
        uint2 u0 = g[(size_t)ssrc[w][j+0] * 32 + l];
        uint2 u1 = g[(size_t)ssrc[w][j+1] * 32 + l];
        uint2 u2 = g[(size_t)ssrc[w][j+2] * 32 + l];
        uint2 u3 = g[(size_t)ssrc[w][j+3] * 32 + l];
        uint2 u4 = g[(size_t)ssrc[w][j+4] * 32 + l];
        uint2 u5 = g[(size_t)ssrc[w][j+5] * 32 + l];
        uint2 u6 = g[(size_t)ssrc[w][j+6] * 32 + l];
        uint2 u7 = g[(size_t)ssrc[w][j+7] * 32 + l];
        float4 v0 = unpack_h4(u0), v1 = unpack_h4(u1), v2 = unpack_h4(u2), v3 = unpack_h4(u3);
        float4 v4 = unpack_h4(u4), v5 = unpack_h4(u5), v6 = unpack_h4(u6), v7 = unpack_h4(u7);
        float n0 = snrm[w][j+0], n1 = snrm[w][j+1], n2 = snrm[w][j+2], n3 = snrm[w][j+3];
        float n4 = snrm[w][j+4], n5 = snrm[w][j+5], n6 = snrm[w][j+6], n7 = snrm[w][j+7];
        acc.x += n0*v0.x + n1*v1.x + n2*v2.x + n3*v3.x + n4*v4.x + n5*v5.x + n6*v6.x + n7*v7.x;
        acc.y += n0*v0.y + n1*v1.y + n2*v2.y + n3*v3.y + n4*v4.y + n5*v5.y + n6*v6.y + n7*v7.y;
        acc.z += n0*v0.z + n1*v1.z + n2*v2.z + n3*v3.z + n4*v4.z + n5*v5.z + n6*v6.z + n7*v7.z;
        acc.w += n0*v0.w + n1*v1.w + n2*v2.w + n3*v3.w + n4*v4.w + n5*v5.w + n6*v6.w + n7*v7.w;
    }
    for (; j < cnt; j++) {
        float4 v = unpack_h4(g[(size_t)ssrc[w][j] * 32 + l]);
        float n0 = snrm[w][j];
        acc.x += n0*v.x; acc.y += n0*v.y; acc.z += n0*v.z; acc.w += n0*v.w;
    }

    if (MODE == 0) {
        ((uint2*)d_t1h)[(size_t)node * 32 + l] = pack_h4(acc);
        store_a4(1, node, l, acc);
    } else {
        float4 xv = ((const float4*)x)[(size_t)node * 32 + l];
        float4 t = make_float4(2.f*acc.x - xv.x, 2.f*acc.y - xv.y,
                               2.f*acc.z - xv.z, 2.f*acc.w - xv.w);
        store_a4(2, node, l, t);
    }
}

// ================= ring-pipelined mma.sync GEMM (fp16, MT=64, 2 CTA/SM) ==
#define SA     0
#define SB     (8 * ACH)                   // 24576
#define S_BIAS (SB + 8 * BCH)              // 79872
#define S_MBF  (S_BIAS + 896)              // full barriers, 8 x 8B
#define S_MBE  (S_MBF + 64)                // empty barriers, 8 x 8B
#define S_TOTAL (S_MBE + 64)               // 80896

__device__ __forceinline__ void consume_chunk(uint32_t sb, int c, int l,
                                              int mbase, int nbase,
                                              float acc[13][4]) {
    uint32_t a[4], bb[14][2];
    uint32_t aBase = sb + SA + c * ACH;
    ldsm4(a, aBase + (mbase + (l & 15)) * AROW + (l >> 4) * 16);
    uint32_t bBase = sb + SB + c * BCH + (l & 15) * BROW + (l >> 4) * 16;
#pragma unroll
    for (int j2 = 0; j2 < 7; j2++)
        ldsm4t(&bb[j2 * 2][0], bBase + (nbase + j2 * 16) * 2);
#pragma unroll
    for (int j = 0; j < 13; j++) mma16816(acc[j], a, bb[j]);
}

// issue the 2 bulk copies for global chunk index t into slot (t & 7); single lane
__device__ __forceinline__ void issue_chunk(uint32_t sb, int t, int tile, int wbase) {
    int kb = t >> 3, c = t & 7;
    int slot = t & 7;
    const char* ga  = (const char*)d_a[kb] + (size_t)tile * ATILE + c * ACH;
    const char* gb  = (const char*)d_wh[wbase + kb] + c * BCH;
    uint32_t mb = sb + S_MBF + slot * 8;
    MBARRIER_EXPECT_TX(mb, ACH + BCH);
    BULK_G2S(sb + SA + slot * ACH, ga, ACH, mb);
    BULK_G2S(sb + SB + slot * BCH, gb, BCH, mb);
}

__global__ __launch_bounds__(256, 2) void gemm_kernel(
    const float* __restrict__ b1, const float* __restrict__ b2, const float* __restrict__ b3,
    float* __restrict__ out, int nnodes)
{
    extern __shared__ char smem[];
    const uint32_t sb = smem_u32(smem);
    const int tid = threadIdx.x;
    const int l = tid & 31;
    const int wid = tid >> 5;
    const int s = blockIdx.y;
    const int tile = blockIdx.x;
    const int bm = tile * MT;
    const int T = 8 * (s + 1);           // total chunks
    const int wbase = s * (s + 1) / 2;
    float* sbias = (float*)(smem + S_BIAS);

    const float* bp = (s == 0) ? b1 : (s == 1) ? b2 : b3;
    if (tid < OD) sbias[tid] = bp[tid];
    if (tid == 0) {
#pragma unroll
        for (int c = 0; c < 8; c++) {
            MBARRIER_INIT(sb + S_MBF + c * 8, 1);   // full: tx-completed
            MBARRIER_INIT(sb + S_MBE + c * 8, 8);   // empty: one arrive per warp
        }
    }
    __syncthreads();

    // prologue: fill all 8 slots (single lane; non-blocking issues)
    if (tid == 0)
        for (int t = 0; t < 8; t++) issue_chunk(sb, t, tile, wbase);

    const int wm = wid >> 1, wn = wid & 1;
    const int mbase = wm * 16, nbase = wn * 104;

    float acc[13][4];
#pragma unroll
    for (int j = 0; j < 13; j++)
#pragma unroll
        for (int r = 0; r < 4; r++) acc[j][r] = 0.f;

    for (int t = 0; t < T; t++) {
        int slot = t & 7;
        int use  = t >> 3;
        MBARRIER_WAIT_PARITY(sb + S_MBF + slot * 8, use & 1);
        consume_chunk(sb, slot, l, mbase, nbase, acc);
        __syncwarp();
        if (l == 0) MBARRIER_ARRIVE(sb + S_MBE + slot * 8);
        // Producer: WHOLE warp 0 executes the blocking empty-wait (warp-uniform,
        // no divergent spin against the next collective); only lane 0 issues.
        if (wid == 0 && t + 8 < T) {
            MBARRIER_WAIT_PARITY(sb + S_MBE + slot * 8, use & 1);
            if (l == 0) issue_chunk(sb, t + 8, tile, wbase);
        }
        __syncwarp();
    }

    // epilogue
    {
        int row0 = bm + mbase + (l >> 2);
#pragma unroll
        for (int j = 0; j < 13; j++) {
            int col = nbase + j * 8 + (l & 3) * 2;
            if (col >= OD) continue;
            float bc0 = sbias[col], bc1 = sbias[col + 1];
            if (row0 < nnodes) {
                float2 v = make_float2(acc[j][0] + bc0, acc[j][1] + bc1);
                *(float2*)(out + ((size_t)s * nnodes + row0) * OD + col) = v;
            }
            int row1 = row0 + 8;
            if (row1 < nnodes) {
                float2 v = make_float2(acc[j][2] + bc0, acc[j][3] + bc1);
                *(float2*)(out + ((size_t)s * nnodes + row1) * OD + col) = v;
            }
        }
    }
}

static inline int cdiv(int a, int b) { return (a + b - 1) / b; }

extern "C" void kernel_launch(void* const* d_in, const int* in_sizes, int n_in,
                              void* d_out, int out_size) {
    const float* x    = (const float*)d_in[0];
    const int*   ei   = (const int*)  d_in[1];
    const float* ew   = (const float*)d_in[2];
    const float* w1_0 = (const float*)d_in[3];
    const float* b1   = (const float*)d_in[4];
    const float* w2_0 = (const float*)d_in[5];
    const float* w2_1 = (const float*)d_in[6];
    const float* b2   = (const float*)d_in[7];
    const float* w3_0 = (const float*)d_in[8];
    const float* w3_1 = (const float*)d_in[9];
    const float* w3_2 = (const float*)d_in[10];
    const float* b3   = (const float*)d_in[11];
    float* out = (float*)d_out;

    int E = in_sizes[2];
    int N = in_sizes[0] / FD;
    if (N > NN) N = NN;
    const int* src = ei;
    const int* dst = ei + E;

    static void* p_deg = nullptr;
    static void* p_cnt = nullptr;
    if (!p_deg) {
        cudaFuncSetAttribute(gemm_kernel, cudaFuncAttributeMaxDynamicSharedMemorySize, S_TOTAL);
        cudaGetSymbolAddress(&p_deg, d_deg);
        cudaGetSymbolAddress(&p_cnt, d_cnt);
    }

    cudaMemsetAsync(p_deg, 0, sizeof(float) * NN);
    cudaMemsetAsync(p_cnt, 0, sizeof(int) * NN);
    deg_kernel<<<cdiv(E, 256), 256>>>(src, ew, E);
    fill_kernel<<<cdiv(E, 256), 256>>>(src, dst, ew, E);
    convert_x_kernel<<<cdiv(N * 32, 256), 256>>>((const float4*)x, N * 32);
    wprep_kernel<<<cdiv(6 * FD * BCOLS, 256), 256>>>(w1_0, w2_0, w2_1, w3_0, w3_1, w3_2);
    spmm_kernel<0><<<cdiv(N, 8), 256>>>(x, N);
    spmm_kernel<1><<<cdiv(N, 8), 256>>>(x, N);

    dim3 grid(NT, 3);
    gemm_kernel<<<grid, 256, S_TOTAL>>>(b1, b2, b3, out, N);
}

// round 14
// speedup vs baseline: 6.0771x; 1.0162x over previous
#include <cuda_runtime.h>
#include <cuda_fp16.h>
#include <cstdint>

// Problem constants: N=50000, E=800000, IN=128, OUT=200
#define NN   50000
#define FD   128
#define OD   200
#define CAP  96
#define MT   128
#define NT   391                   // M tiles (128 rows each)
// A operand image (fp16): [tile][chunk ks 0..7][row 0..127][48B], 32B data + 16B pad
#define AROW   48
#define ACH    (MT * AROW)         // 6144 B per chunk
#define ATILE  (8 * ACH)           // 49152 B per tile
#define AELEMS ((size_t)NT * ATILE / 2)
// B (weight) image (fp16): [k 0..127][216 cols] row 432B; chunk = 16 rows = 6912B
#define BCOLS  216
#define BROW   (BCOLS * 2)         // 432
#define BCH    (16 * BROW)         // 6912
#define BELEMS ((size_t)FD * BCOLS)
#define SLOTS  16                  // ring depth: 2 full K-blocks in flight

// ================= device scratch (no cudaMalloc allowed) ================
__device__ float d_deg[NN];
__device__ int   d_cnt[NN];
__device__ int2  d_bkt[(size_t)NN * CAP];     // packed (src, norm-as-int)
// row-major fp16 copies for gathers (256B per node row)
__device__ __align__(16) __half d_xh[(size_t)NN * FD];
__device__ __align__(16) __half d_t1h[(size_t)NN * FD];
// chunk-major fp16 operand images of tx0(x), tx1, tx2 (zero-init covers pad rows)
__device__ __align__(1024) __half d_a[3][AELEMS];
// weights fp16, order: w1_0, w2_0, w2_1, w3_0, w3_1, w3_2
__device__ __align__(1024) __half d_wh[6][BELEMS];

// ================= helpers ==============================================
__device__ __forceinline__ uint32_t smem_u32(const void* p) {
    uint32_t a;
    asm("{ .reg .u64 t; cvta.to.shared.u64 t, %1; cvt.u32.u64 %0, t; }" : "=r"(a) : "l"(p));
    return a;
}
#define MBARRIER_INIT(mb, c) \
    asm volatile("mbarrier.init.shared.b64 [%0], %1;" :: "r"((uint32_t)(mb)), "r"((uint32_t)(c)) : "memory")
#define MBARRIER_EXPECT_TX(mb, tx) \
    asm volatile("mbarrier.arrive.expect_tx.shared.b64 _, [%0], %1;" :: "r"((uint32_t)(mb)), "r"((uint32_t)(tx)) : "memory")
#define MBARRIER_ARRIVE(mb) \
    asm volatile("mbarrier.arrive.shared.b64 _, [%0];" :: "r"((uint32_t)(mb)) : "memory")
#define BULK_G2S(dst, src, bytes, mb) \
    asm volatile("cp.async.bulk.shared::cta.global.mbarrier::complete_tx::bytes [%0], [%1], %2, [%3];" \
        :: "r"((uint32_t)(dst)), "l"(src), "r"((uint32_t)(bytes)), "r"((uint32_t)(mb)) : "memory")
#define MBARRIER_WAIT_PARITY(mb, ph) do {                                        \
    uint32_t _mb = (uint32_t)(mb), _ph = (uint32_t)(ph), _done;                  \
    asm volatile("{\n\t.reg .pred p;\n\t"                                        \
        "mbarrier.try_wait.parity.acquire.cta.shared::cta.b64 p, [%1], %2;\n\t"  \
        "selp.b32 %0, 1, 0, p;\n\t}" : "=r"(_done) : "r"(_mb), "r"(_ph) : "memory"); \
    if (!_done) {                                                                \
        asm volatile("{\n\t.reg .pred P1;\n\t"                                   \
            "W%=:\n\t"                                                           \
            "mbarrier.try_wait.parity.acquire.cta.shared::cta.b64 P1, [%0], %1, 0x989680;\n\t" \
            "@P1 bra.uni D%=;\n\t"                                               \
            "bra.uni W%=;\n\t"                                                   \
            "D%=:\n\t}" :: "r"(_mb), "r"(_ph) : "memory");                       \
    }                                                                            \
} while (0)

__device__ __forceinline__ void ldsm4(uint32_t* r, uint32_t addr) {
    asm volatile("ldmatrix.sync.aligned.m8n8.x4.shared.b16 {%0,%1,%2,%3}, [%4];"
                 : "=r"(r[0]), "=r"(r[1]), "=r"(r[2]), "=r"(r[3]) : "r"(addr));
}
__device__ __forceinline__ void ldsm4t(uint32_t* r, uint32_t addr) {
    asm volatile("ldmatrix.sync.aligned.m8n8.x4.trans.shared.b16 {%0,%1,%2,%3}, [%4];"
                 : "=r"(r[0]), "=r"(r[1]), "=r"(r[2]), "=r"(r[3]) : "r"(addr));
}
__device__ __forceinline__ void mma16816(float* c, const uint32_t* a, const uint32_t* b) {
    asm volatile("mma.sync.aligned.m16n8k16.row.col.f32.f16.f16.f32 "
                 "{%0,%1,%2,%3}, {%4,%5,%6,%7}, {%8,%9}, {%0,%1,%2,%3};"
                 : "+f"(c[0]), "+f"(c[1]), "+f"(c[2]), "+f"(c[3])
                 : "r"(a[0]), "r"(a[1]), "r"(a[2]), "r"(a[3]), "r"(b[0]), "r"(b[1]));
}

// ================= graph preprocessing ==================================
__global__ void deg_kernel(const int* __restrict__ src, const float* __restrict__ w, int E) {
    int e = blockIdx.x * blockDim.x + threadIdx.x;
    if (e < E) atomicAdd(&d_deg[src[e]], w[e]);
}
__global__ void fill_kernel(const int* __restrict__ src, const int* __restrict__ dst,
                            const float* __restrict__ w, int E) {
    int e = blockIdx.x * blockDim.x + threadIdx.x;
    if (e >= E) return;
    int s = src[e], d = dst[e];
    float ds = d_deg[s], dd = d_deg[d];
    float is = ds > 0.f ? rsqrtf(ds) : 0.f;
    float id = dd > 0.f ? rsqrtf(dd) : 0.f;
    float nrm = -is * w[e] * id;
    int slot = atomicAdd(&d_cnt[d], 1);
    if (slot < CAP)
        d_bkt[(size_t)d * CAP + slot] = make_int2(s, __float_as_int(nrm));
}

// pack a float4 to fp16 uint2
__device__ __forceinline__ uint2 pack_h4(float4 v) {
    __half2 p0 = __floats2half2_rn(v.x, v.y);
    __half2 p1 = __floats2half2_rn(v.z, v.w);
    return make_uint2(*(uint32_t*)&p0, *(uint32_t*)&p1);
}
// store a float4 (features l*4..l*4+3 of one node row) into op's fp16 A image
__device__ __forceinline__ void store_a4(int op, int node, int l, float4 v) {
    int tile = node >> 7, r = node & 127, ks = l >> 2;
    size_t e = ((size_t)(tile * 8 + ks) * MT + r) * 24 + (l & 3) * 4;
    *(uint2*)&d_a[op][e] = pack_h4(v);
}
// unpack uint2 (4 fp16) -> float4
__device__ __forceinline__ float4 unpack_h4(uint2 u) {
    float2 f0 = __half22float2(*(__half2*)&u.x);
    float2 f1 = __half22float2(*(__half2*)&u.y);
    return make_float4(f0.x, f0.y, f1.x, f1.y);
}

// x fp32 -> x_h row-major fp16 + A image op0
__global__ void convert_x_kernel(const float4* __restrict__ x4, int nwords) {
    int i = blockIdx.x * blockDim.x + threadIdx.x;
    if (i >= nwords) return;
    int node = i >> 5, l = i & 31;
    float4 v = x4[i];
    ((uint2*)d_xh)[i] = pack_h4(v);
    store_a4(0, node, l, v);
}

// weights fp32 [k=128][n=200] -> fp16 [k=128][n=216] zero padded
__global__ void wprep_kernel(const float* w0, const float* w1, const float* w2,
                             const float* w3, const float* w4, const float* w5) {
    const float* ws[6] = {w0, w1, w2, w3, w4, w5};
    int i = blockIdx.x * blockDim.x + threadIdx.x;
    if (i >= 6 * FD * BCOLS) return;
    int m = i / (FD * BCOLS);
    int r = i % (FD * BCOLS);
    int k = r / BCOLS, n = r % BCOLS;
    float v = (n < OD) ? ws[m][(size_t)k * OD + n] : 0.f;
    d_wh[m][r] = __float2half_rn(v);
}

// gather SpMM (fp16 gather, fp32 accumulate), warp-per-node, 4 features/lane, MLP=8.
// MODE 0: tx1 = L^x    -> t1h row-major + A image op1   (gathers d_xh)
// MODE 1: tx2 = 2 L^ tx1 - x -> A image op2             (gathers d_t1h)
template <int MODE>
__global__ __launch_bounds__(256) void spmm_kernel(const float* __restrict__ x, int nnodes) {
    __shared__ int   ssrc[8][CAP];
    __shared__ float snrm[8][CAP];
    int w = threadIdx.x >> 5, l = threadIdx.x & 31;
    int node = blockIdx.x * 8 + w;
    if (node >= nnodes) return;

    int cnt = d_cnt[node];
    if (cnt > CAP) cnt = CAP;
    for (int j = l; j < cnt; j += 32) {
        int2 b = d_bkt[(size_t)node * CAP + j];
        ssrc[w][j] = b.x;
        snrm[w][j] = __int_as_float(b.y);
    }
    __syncwarp();

    const uint2* g = (MODE == 0) ? (const uint2*)d_xh : (const uint2*)d_t1h;
    float4 acc = make_float4(0.f, 0.f, 0.f, 0.f);
    int j = 0;
    for (; j + 8 <= cnt; j += 8) {
        uint2 u0 = g[(size_t)ssrc[w][j+0] * 32 + l];
        uint2 u1 = g[(size_t)ssrc[w][j+1] * 32 + l];
        uint2 u2 = g[(size_t)ssrc[w][j+2] * 32 + l];
        uint2 u3 = g[(size_t)ssrc[w][j+3] * 32 + l];
        uint2 u4 = g[(size_t)ssrc[w][j+4] * 32 + l];
        uint2 u5 = g[(size_t)ssrc[w][j+5] * 32 + l];
        uint2 u6 = g[(size_t)ssrc[w][j+6] * 32 + l];
        uint2 u7 = g[(size_t)ssrc[w][j+7] * 32 + l];
        float4 v0 = unpack_h4(u0), v1 = unpack_h4(u1), v2 = unpack_h4(u2), v3 = unpack_h4(u3);
        float4 v4 = unpack_h4(u4), v5 = unpack_h4(u5), v6 = unpack_h4(u6), v7 = unpack_h4(u7);
        float n0 = snrm[w][j+0], n1 = snrm[w][j+1], n2 = snrm[w][j+2], n3 = snrm[w][j+3];
        float n4 = snrm[w][j+4], n5 = snrm[w][j+5], n6 = snrm[w][j+6], n7 = snrm[w][j+7];
        acc.x += n0*v0.x + n1*v1.x + n2*v2.x + n3*v3.x + n4*v4.x + n5*v5.x + n6*v6.x + n7*v7.x;
        acc.y += n0*v0.y + n1*v1.y + n2*v2.y + n3*v3.y + n4*v4.y + n5*v5.y + n6*v6.y + n7*v7.y;
        acc.z += n0*v0.z + n1*v1.z + n2*v2.z + n3*v3.z + n4*v4.z + n5*v5.z + n6*v6.z + n7*v7.z;
        acc.w += n0*v0.w + n1*v1.w + n2*v2.w + n3*v3.w + n4*v4.w + n5*v5.w + n6*v6.w + n7*v7.w;
    }
    for (; j < cnt; j++) {
        float4 v = unpack_h4(g[(size_t)ssrc[w][j] * 32 + l]);
        float n0 = snrm[w][j];
        acc.x += n0*v.x; acc.y += n0*v.y; acc.z += n0*v.z; acc.w += n0*v.w;
    }

    if (MODE == 0) {
        ((uint2*)d_t1h)[(size_t)node * 32 + l] = pack_h4(acc);
        store_a4(1, node, l, acc);
    } else {
        float4 xv = ((const float4*)x)[(size_t)node * 32 + l];
        float4 t = make_float4(2.f*acc.x - xv.x, 2.f*acc.y - xv.y,
                               2.f*acc.z - xv.z, 2.f*acc.w - xv.w);
        store_a4(2, node, l, t);
    }
}

// ============ deep-ring mma.sync GEMM (fp16, MT=128, 16 slots) ===========
#define SA     0
#define SB     (SLOTS * ACH)               // 98304
#define S_BIAS (SB + SLOTS * BCH)          // 208896
#define S_MBF  (S_BIAS + 896)              // full barriers, 16 x 8B
#define S_MBE  (S_MBF + 128)               // empty barriers, 16 x 8B
#define S_TOTAL (S_MBE + 128)              // 210048

__device__ __forceinline__ void consume_chunk(uint32_t sb, int slot, int l,
                                              int mbase, int nbase,
                                              float acc[2][13][4]) {
    uint32_t a[2][4], bb[14][2];
    uint32_t aBase = sb + SA + slot * ACH;
#pragma unroll
    for (int i = 0; i < 2; i++)
        ldsm4(a[i], aBase + (mbase + i * 16 + (l & 15)) * AROW + (l >> 4) * 16);
    uint32_t bBase = sb + SB + slot * BCH + (l & 15) * BROW + (l >> 4) * 16;
#pragma unroll
    for (int j2 = 0; j2 < 7; j2++)
        ldsm4t(&bb[j2 * 2][0], bBase + (nbase + j2 * 16) * 2);
#pragma unroll
    for (int i = 0; i < 2; i++)
#pragma unroll
        for (int j = 0; j < 13; j++) mma16816(acc[i][j], a[i], bb[j]);
}

// issue the 2 bulk copies for global chunk index t into slot (t & 15); single lane
__device__ __forceinline__ void issue_chunk(uint32_t sb, int t, int tile, int wbase) {
    int kb = t >> 3, c = t & 7;
    int slot = t & (SLOTS - 1);
    const char* ga  = (const char*)d_a[kb] + (size_t)tile * ATILE + c * ACH;
    const char* gb  = (const char*)d_wh[wbase + kb] + c * BCH;
    uint32_t mb = sb + S_MBF + slot * 8;
    MBARRIER_EXPECT_TX(mb, ACH + BCH);
    BULK_G2S(sb + SA + slot * ACH, ga, ACH, mb);
    BULK_G2S(sb + SB + slot * BCH, gb, BCH, mb);
}

__global__ __launch_bounds__(256, 1) void gemm_kernel(
    const float* __restrict__ b1, const float* __restrict__ b2, const float* __restrict__ b3,
    float* __restrict__ out, int nnodes)
{
    extern __shared__ char smem[];
    const uint32_t sb = smem_u32(smem);
    const int tid = threadIdx.x;
    const int l = tid & 31;
    const int wid = tid >> 5;
    const int s = blockIdx.y;
    const int tile = blockIdx.x;
    const int bm = tile * MT;
    const int T = 8 * (s + 1);           // total chunks (8, 16, 24)
    const int wbase = s * (s + 1) / 2;
    float* sbias = (float*)(smem + S_BIAS);

    const float* bp = (s == 0) ? b1 : (s == 1) ? b2 : b3;
    if (tid < OD) sbias[tid] = bp[tid];
    if (tid == 0) {
#pragma unroll
        for (int c = 0; c < SLOTS; c++) {
            MBARRIER_INIT(sb + S_MBF + c * 8, 1);   // full: tx-completed
            MBARRIER_INIT(sb + S_MBE + c * 8, 8);   // empty: one arrive per warp
        }
    }
    __syncthreads();

    // prologue: fill up to SLOTS slots (single lane; non-blocking issues)
    const int P = (T < SLOTS) ? T : SLOTS;
    if (tid == 0)
        for (int t = 0; t < P; t++) issue_chunk(sb, t, tile, wbase);

    const int wm = wid >> 1, wn = wid & 1;
    const int mbase = wm * 32, nbase = wn * 104;

    float acc[2][13][4];
#pragma unroll
    for (int i = 0; i < 2; i++)
#pragma unroll
        for (int j = 0; j < 13; j++)
#pragma unroll
            for (int r = 0; r < 4; r++) acc[i][j][r] = 0.f;

    for (int t = 0; t < T; t++) {
        int slot = t & (SLOTS - 1);
        int use  = t >> 4;
        MBARRIER_WAIT_PARITY(sb + S_MBF + slot * 8, use & 1);
        consume_chunk(sb, slot, l, mbase, nbase, acc);
        __syncwarp();
        if (l == 0) MBARRIER_ARRIVE(sb + S_MBE + slot * 8);
        // Producer: WHOLE warp 0 executes the blocking empty-wait (warp-uniform,
        // no divergent spin against the next collective); only lane 0 issues.
        if (wid == 0 && t + SLOTS < T) {
            MBARRIER_WAIT_PARITY(sb + S_MBE + slot * 8, use & 1);
            if (l == 0) issue_chunk(sb, t + SLOTS, tile, wbase);
        }
        __syncwarp();
    }

    // epilogue
#pragma unroll
    for (int i = 0; i < 2; i++) {
        int row0 = bm + mbase + i * 16 + (l >> 2);
#pragma unroll
        for (int j = 0; j < 13; j++) {
            int col = nbase + j * 8 + (l & 3) * 2;
            if (col >= OD) continue;
            float bc0 = sbias[col], bc1 = sbias[col + 1];
            if (row0 < nnodes) {
                float2 v = make_float2(acc[i][j][0] + bc0, acc[i][j][1] + bc1);
                *(float2*)(out + ((size_t)s * nnodes + row0) * OD + col) = v;
            }
            int row1 = row0 + 8;
            if (row1 < nnodes) {
                float2 v = make_float2(acc[i][j][2] + bc0, acc[i][j][3] + bc1);
                *(float2*)(out + ((size_t)s * nnodes + row1) * OD + col) = v;
            }
        }
    }
}

static inline int cdiv(int a, int b) { return (a + b - 1) / b; }

extern "C" void kernel_launch(void* const* d_in, const int* in_sizes, int n_in,
                              void* d_out, int out_size) {
    const float* x    = (const float*)d_in[0];
    const int*   ei   = (const int*)  d_in[1];
    const float* ew   = (const float*)d_in[2];
    const float* w1_0 = (const float*)d_in[3];
    const float* b1   = (const float*)d_in[4];
    const float* w2_0 = (const float*)d_in[5];
    const float* w2_1 = (const float*)d_in[6];
    const float* b2   = (const float*)d_in[7];
    const float* w3_0 = (const float*)d_in[8];
    const float* w3_1 = (const float*)d_in[9];
    const float* w3_2 = (const float*)d_in[10];
    const float* b3   = (const float*)d_in[11];
    float* out = (float*)d_out;

    int E = in_sizes[2];
    int N = in_sizes[0] / FD;
    if (N > NN) N = NN;
    const int* src = ei;
    const int* dst = ei + E;

    static void* p_deg = nullptr;
    static void* p_cnt = nullptr;
    if (!p_deg) {
        cudaFuncSetAttribute(gemm_kernel, cudaFuncAttributeMaxDynamicSharedMemorySize, S_TOTAL);
        cudaGetSymbolAddress(&p_deg, d_deg);
        cudaGetSymbolAddress(&p_cnt, d_cnt);
    }

    cudaMemsetAsync(p_deg, 0, sizeof(float) * NN);
    cudaMemsetAsync(p_cnt, 0, sizeof(int) * NN);
    deg_kernel<<<cdiv(E, 256), 256>>>(src, ew, E);
    fill_kernel<<<cdiv(E, 256), 256>>>(src, dst, ew, E);
    convert_x_kernel<<<cdiv(N * 32, 256), 256>>>((const float4*)x, N * 32);
    wprep_kernel<<<cdiv(6 * FD * BCOLS, 256), 256>>>(w1_0, w2_0, w2_1, w3_0, w3_1, w3_2);
    spmm_kernel<0><<<cdiv(N, 8), 256>>>(x, N);
    spmm_kernel<1><<<cdiv(N, 8), 256>>>(x, N);

    dim3 grid(NT, 3);
    gemm_kernel<<<grid, 256, S_TOTAL>>>(b1, b2, b3, out, N);
}